// round 8
// baseline (speedup 1.0000x reference)
#include <cuda_runtime.h>
#include <cuda_bf16.h>
#include <cstdint>
#include <cstddef>

#define IN_DIM   1024
#define HID_DIM  512
#define OUT_DIM  1024
#define N_EXP    6
#define H3       3072
#define MAXB     32768

// ---------------- scratch (device globals; no allocation allowed) ----------
__device__ float         g_gate[(size_t)MAXB * N_EXP];
__device__ __nv_bfloat16 g_xhi [(size_t)MAXB * IN_DIM];
__device__ uint8_t       g_xh8 [(size_t)MAXB * IN_DIM];   // e4m3(x)
__device__ uint8_t       g_xl8 [(size_t)MAXB * IN_DIM];   // e5m2(x - bf16(x))
__device__ __nv_bfloat16 g_w1hi[(size_t)H3 * IN_DIM];     // [3072,1024] N-major, K contig
__device__ uint8_t       g_w1h8[(size_t)H3 * IN_DIM];
__device__ uint8_t       g_w1l8[(size_t)H3 * IN_DIM];
__device__ __nv_bfloat16 g_w2hi[(size_t)OUT_DIM * H3];    // [1024,3072]
__device__ uint8_t       g_w2h8[(size_t)OUT_DIM * H3];
__device__ uint8_t       g_w2l8[(size_t)OUT_DIM * H3];
__device__ __nv_bfloat16 g_hshi[(size_t)MAXB * H3];
__device__ uint8_t       g_hsh8[(size_t)MAXB * H3];
__device__ uint8_t       g_hsl8[(size_t)MAXB * H3];

// ---------------- helpers ---------------------------------------------------
__device__ __forceinline__ uint32_t smem_u32(const void* p) {
    uint32_t a;
    asm("{ .reg .u64 t; cvta.to.shared.u64 t, %1; cvt.u32.u64 %0, t; }" : "=r"(a) : "l"(p));
    return a;
}
__device__ __forceinline__ void cp16(uint32_t dst, const void* src) {
    asm volatile("cp.async.cg.shared.global [%0], [%1], 16;" :: "r"(dst), "l"(src));
}
__device__ __forceinline__ void cp_commit() {
    asm volatile("cp.async.commit_group;" ::: "memory");
}
template <int N>
__device__ __forceinline__ void cp_wait() {
    asm volatile("cp.async.wait_group %0;" :: "n"(N) : "memory");
}
__device__ __forceinline__ void ldsm4(uint32_t* r, uint32_t addr) {
    asm volatile("ldmatrix.sync.aligned.m8n8.x4.shared.b16 {%0,%1,%2,%3}, [%4];"
                 : "=r"(r[0]), "=r"(r[1]), "=r"(r[2]), "=r"(r[3]) : "r"(addr));
}
__device__ __forceinline__ void mma_bf16(float* c, const uint32_t* a, const uint32_t* b) {
    asm volatile(
        "mma.sync.aligned.m16n8k16.row.col.f32.bf16.bf16.f32 "
        "{%0,%1,%2,%3}, {%4,%5,%6,%7}, {%8,%9}, {%0,%1,%2,%3};"
        : "+f"(c[0]), "+f"(c[1]), "+f"(c[2]), "+f"(c[3])
        : "r"(a[0]), "r"(a[1]), "r"(a[2]), "r"(a[3]), "r"(b[0]), "r"(b[1]));
}
// fp8 cross-term MMAs: k32, fp32 acc shared with the bf16 pass.
__device__ __forceinline__ void mma_f8_45(float* c, const uint32_t* a, const uint32_t* b) {
    asm volatile(
        "mma.sync.aligned.m16n8k32.row.col.f32.e4m3.e5m2.f32 "
        "{%0,%1,%2,%3}, {%4,%5,%6,%7}, {%8,%9}, {%0,%1,%2,%3};"
        : "+f"(c[0]), "+f"(c[1]), "+f"(c[2]), "+f"(c[3])
        : "r"(a[0]), "r"(a[1]), "r"(a[2]), "r"(a[3]), "r"(b[0]), "r"(b[1]));
}
__device__ __forceinline__ void mma_f8_54(float* c, const uint32_t* a, const uint32_t* b) {
    asm volatile(
        "mma.sync.aligned.m16n8k32.row.col.f32.e5m2.e4m3.f32 "
        "{%0,%1,%2,%3}, {%4,%5,%6,%7}, {%8,%9}, {%0,%1,%2,%3};"
        : "+f"(c[0]), "+f"(c[1]), "+f"(c[2]), "+f"(c[3])
        : "r"(a[0]), "r"(a[1]), "r"(a[2]), "r"(a[3]), "r"(b[0]), "r"(b[1]));
}
// packers: first src -> HIGH byte, second -> LOW byte
__device__ __forceinline__ uint16_t pk_e4m3(float hi, float lo) {
    uint16_t r;
    asm("cvt.rn.satfinite.e4m3x2.f32 %0, %1, %2;" : "=h"(r) : "f"(hi), "f"(lo));
    return r;
}
__device__ __forceinline__ uint16_t pk_e5m2(float hi, float lo) {
    uint16_t r;
    asm("cvt.rn.satfinite.e5m2x2.f32 %0, %1, %2;" : "=h"(r) : "f"(hi), "f"(lo));
    return r;
}
// bf16 tile: 64B rows, 16B chunks, xor-swizzle (conflict-free ldmatrix)
__device__ __forceinline__ int sw_off(int row, int chunk) {
    return row * 64 + ((chunk ^ ((row >> 1) & 3)) << 4);
}
// fp8 tile: 32B rows, 2 chunks; 8 consecutive rows at fixed chunk hit 8
// distinct 16B slots mod 128B
__device__ __forceinline__ int f8_off(int row, int chunk) {
    return row * 32 + ((chunk ^ ((row >> 2) & 1)) << 4);
}

// ---------------- fused gate + x split (one pass over x) -------------------
__global__ __launch_bounds__(256) void gate_split_kernel(
    const float* __restrict__ x,
    const float* __restrict__ g2w, const float* __restrict__ g2b,
    const float* __restrict__ g3w, const float* __restrict__ g3b,
    float* __restrict__ gate,
    __nv_bfloat16* __restrict__ xhi, uint8_t* __restrict__ xh8,
    uint8_t* __restrict__ xl8, int B)
{
    int row  = (blockIdx.x * 256 + threadIdx.x) >> 5;
    int lane = threadIdx.x & 31;
    if (row >= B) return;

    const float4* xr = reinterpret_cast<const float4*>(x + (size_t)row * IN_DIM);
    float a0 = 0.f, a1 = 0.f, a2 = 0.f, a3 = 0.f;
    #pragma unroll
    for (int j = 0; j < 8; ++j) {
        int i = lane + j * 32;
        float4 v = xr[i];
        int k = i * 4;
        a0 = fmaf(v.x, g2w[k], fmaf(v.y, g2w[k+1], fmaf(v.z, g2w[k+2], fmaf(v.w, g2w[k+3], a0))));
        a1 = fmaf(v.x, g3w[k*3+0], fmaf(v.y, g3w[(k+1)*3+0], fmaf(v.z, g3w[(k+2)*3+0], fmaf(v.w, g3w[(k+3)*3+0], a1))));
        a2 = fmaf(v.x, g3w[k*3+1], fmaf(v.y, g3w[(k+1)*3+1], fmaf(v.z, g3w[(k+2)*3+1], fmaf(v.w, g3w[(k+3)*3+1], a2))));
        a3 = fmaf(v.x, g3w[k*3+2], fmaf(v.y, g3w[(k+1)*3+2], fmaf(v.z, g3w[(k+2)*3+2], fmaf(v.w, g3w[(k+3)*3+2], a3))));
        float vv[4] = {v.x, v.y, v.z, v.w};
        __nv_bfloat16 hb[4];
        float lf[4];
        uint32_t ph[2];
        #pragma unroll
        for (int q = 0; q < 4; ++q) {
            hb[q] = __float2bfloat16(vv[q]);
            lf[q] = vv[q] - __bfloat162float(hb[q]);
        }
        ph[0] = (uint32_t)__bfloat16_as_ushort(hb[0]) | ((uint32_t)__bfloat16_as_ushort(hb[1]) << 16);
        ph[1] = (uint32_t)__bfloat16_as_ushort(hb[2]) | ((uint32_t)__bfloat16_as_ushort(hb[3]) << 16);
        *reinterpret_cast<uint2*>(xhi + (size_t)row * IN_DIM + k) = make_uint2(ph[0], ph[1]);
        uint32_t h8 = (uint32_t)pk_e4m3(vv[1], vv[0]) | ((uint32_t)pk_e4m3(vv[3], vv[2]) << 16);
        uint32_t l8 = (uint32_t)pk_e5m2(lf[1], lf[0]) | ((uint32_t)pk_e5m2(lf[3], lf[2]) << 16);
        *reinterpret_cast<uint32_t*>(xh8 + (size_t)row * IN_DIM + k) = h8;
        *reinterpret_cast<uint32_t*>(xl8 + (size_t)row * IN_DIM + k) = l8;
    }
    #pragma unroll
    for (int off = 16; off > 0; off >>= 1) {
        a0 += __shfl_down_sync(0xffffffffu, a0, off);
        a1 += __shfl_down_sync(0xffffffffu, a1, off);
        a2 += __shfl_down_sync(0xffffffffu, a2, off);
        a3 += __shfl_down_sync(0xffffffffu, a3, off);
    }
    if (lane == 0) {
        float alpha = 1.f / (1.f + expf(-(a0 + g2b[0])));
        float l0 = a1 + g3b[0], l1 = a2 + g3b[1], l2 = a3 + g3b[2];
        float m = fmaxf(l0, fmaxf(l1, l2));
        float e0 = expf(l0 - m), e1 = expf(l1 - m), e2 = expf(l2 - m);
        float inv = 1.f / (e0 + e1 + e2);
        float p0 = e0 * inv, p1 = e1 * inv, p2 = e2 * inv, ga = 1.f - alpha;
        float* o = gate + (size_t)row * N_EXP;
        o[0] = ga * p0;    o[1] = ga * p1;    o[2] = ga * p2;
        o[3] = alpha * p0; o[4] = alpha * p1; o[5] = alpha * p2;
    }
}

// ---------------- transpose + split: src[R,C] fp32 -> [C,R] bf16 + fp8 ------
__global__ void transplit_kernel(const float* __restrict__ src,
                                 __nv_bfloat16* __restrict__ dhi,
                                 uint8_t* __restrict__ dh8,
                                 uint8_t* __restrict__ dl8, int R, int C)
{
    __shared__ float t[32][33];
    size_t zoff = (size_t)blockIdx.z * R * C;
    int c0 = blockIdx.x * 32, r0 = blockIdx.y * 32;
    int tx = threadIdx.x, ty = threadIdx.y;          // 32 x 8
    #pragma unroll
    for (int i = 0; i < 4; ++i)
        t[ty + i*8][tx] = src[zoff + (size_t)(r0 + ty + i*8) * C + c0 + tx];
    __syncthreads();
    #pragma unroll
    for (int i = 0; i < 4; ++i) {
        int c = c0 + ty + i*8, r = r0 + tx;
        float v = t[tx][ty + i*8];
        __nv_bfloat16 h = __float2bfloat16(v);
        float l = v - __bfloat162float(h);
        dhi[zoff + (size_t)c * R + r] = h;
        dh8[zoff + (size_t)c * R + r] = (uint8_t)(pk_e4m3(0.f, v) & 0xFF);
        dl8[zoff + (size_t)c * R + r] = (uint8_t)(pk_e5m2(0.f, l) & 0xFF);
    }
}

// ---------------- split bf16+fp8 MMA GEMM -----------------------------------
// CTA tile 128x128, BK=32, 8 warps (2M x 4N), warp tile 64x32, fp32 acc.
// acc += Ahi*Bhi (bf16 k16 x2) + e4m3(A)*e5m2(Blo) + e5m2(Alo)*e4m3(B) (k32).
// Stage 32KB: Ahi 8K | Bhi 8K | A8h 4K | A8l 4K | B8h 4K | B8l 4K.
#define BM 128
#define BN 128
#define BK 32
#define STAGES 3
#define STAGE_BYTES 32768
#define SMEM_TOTAL (STAGES * STAGE_BYTES)

template <int K, bool FIRST>
__global__ __launch_bounds__(256, 2) void gemm_mma(
    const __nv_bfloat16* __restrict__ Ahi, const uint8_t* __restrict__ A8hg,
    const uint8_t* __restrict__ A8lg,
    const __nv_bfloat16* __restrict__ Bhi, const uint8_t* __restrict__ B8hg,
    const uint8_t* __restrict__ B8lg,
    const float* __restrict__ bias, const float* __restrict__ gate,
    __nv_bfloat16* __restrict__ Chi, uint8_t* __restrict__ Ch8,
    uint8_t* __restrict__ Cl8, float* __restrict__ Cf)
{
    extern __shared__ char smem[];
    const uint32_t sbase = smem_u32(smem);
    const int tid  = threadIdx.x;
    const int wid  = tid >> 5;
    const int lane = tid & 31;
    const int mBlk = blockIdx.y * BM;
    const int nBlk = blockIdx.x * BN;
    const int wm = (wid >> 2) * 64;
    const int wn = (wid & 3) * 32;
    constexpr int NK = K / BK;

    const __nv_bfloat16* bfTab[2] = { Ahi + (size_t)mBlk * K, Bhi + (size_t)nBlk * K };
    const uint8_t* f8Tab[4] = { A8hg + (size_t)mBlk * K, A8lg + (size_t)mBlk * K,
                                B8hg + (size_t)nBlk * K, B8lg + (size_t)nBlk * K };

    float acc[4][4][4];
    #pragma unroll
    for (int i = 0; i < 4; ++i)
        #pragma unroll
        for (int j = 0; j < 4; ++j)
            #pragma unroll
            for (int q = 0; q < 4; ++q) acc[i][j][q] = 0.f;

    auto load_stage = [&](int s) {
        const int k0 = s * BK;
        const uint32_t sb = sbase + (s % STAGES) * STAGE_BYTES;
        // bf16: 1024 chunks (A 512, B 512)
        #pragma unroll
        for (int j = 0; j < 4; ++j) {
            int idx = tid + j * 256;
            int reg = idx >> 9;
            int i = idx & 511;
            int row = i >> 2, c = i & 3;
            cp16(sb + reg * 8192 + sw_off(row, c),
                 bfTab[reg] + (size_t)row * K + k0 + c * 8);
        }
        // fp8: 1024 chunks (4 regions x 256)
        #pragma unroll
        for (int j = 0; j < 4; ++j) {
            int idx = tid + j * 256;
            int reg = idx >> 8;
            int i = idx & 255;
            int row = i >> 1, c = i & 1;
            cp16(sb + 16384 + reg * 4096 + f8_off(row, c),
                 f8Tab[reg] + (size_t)row * K + k0 + c * 16);
        }
        cp_commit();
    };

    #pragma unroll
    for (int s = 0; s < STAGES - 1; ++s) load_stage(s);

    const int rA = wm + (lane & 15);
    const int rB = wn + ((lane >> 4) << 3) + (lane & 7);
    const int cAoff = lane >> 4;
    const int cBoff = (lane >> 3) & 1;
    const int r8 = lane & 15;          // fp8 ldsm row-in-group
    const int c8 = lane >> 4;          // fp8 ldsm chunk

    #pragma unroll 3
    for (int s = 0; s < NK; ++s) {
        cp_wait<STAGES - 2>();
        __syncthreads();
        const uint32_t sb = sbase + (s % STAGES) * STAGE_BYTES;

        // bf16 kk0 hi frags — restart tensor pipe first
        uint32_t Ah[4][4], Bh[4][2];
        #pragma unroll
        for (int mi = 0; mi < 4; ++mi)
            ldsm4(Ah[mi], sb + sw_off(rA + 16 * mi, cAoff));
        #pragma unroll
        for (int jp = 0; jp < 2; ++jp) {
            uint32_t t[4];
            ldsm4(t, sb + 8192 + sw_off(rB + 16 * jp, cBoff));
            Bh[2*jp][0] = t[0]; Bh[2*jp][1] = t[1];
            Bh[2*jp+1][0] = t[2]; Bh[2*jp+1][1] = t[3];
        }

        if (s + STAGES - 1 < NK) load_stage(s + STAGES - 1);
        else cp_commit();

        // fp8 set 1: A hi_e4 + B lo_e5
        uint32_t A8h[4][4], B8l[4][2];
        #pragma unroll
        for (int mi = 0; mi < 4; ++mi)
            ldsm4(A8h[mi], sb + 16384 + f8_off(wm + 16 * mi + r8, c8));
        #pragma unroll
        for (int jp = 0; jp < 2; ++jp) {
            uint32_t t[4];
            ldsm4(t, sb + 28672 + f8_off(wn + 16 * jp + r8, c8));
            B8l[2*jp][0] = t[0]; B8l[2*jp][1] = t[2];
            B8l[2*jp+1][0] = t[1]; B8l[2*jp+1][1] = t[3];
        }

        // pass 1: hi*hi kk0
        #pragma unroll
        for (int mi = 0; mi < 4; ++mi)
            #pragma unroll
            for (int nj = 0; nj < 4; ++nj)
                mma_bf16(acc[mi][nj], Ah[mi], Bh[nj]);

        // bf16 kk1 frags
        uint32_t Ah1[4][4], Bh1[4][2];
        #pragma unroll
        for (int mi = 0; mi < 4; ++mi)
            ldsm4(Ah1[mi], sb + sw_off(rA + 16 * mi, 2 + cAoff));
        #pragma unroll
        for (int jp = 0; jp < 2; ++jp) {
            uint32_t t[4];
            ldsm4(t, sb + 8192 + sw_off(rB + 16 * jp, 2 + cBoff));
            Bh1[2*jp][0] = t[0]; Bh1[2*jp][1] = t[1];
            Bh1[2*jp+1][0] = t[2]; Bh1[2*jp+1][1] = t[3];
        }

        // pass 2: cross hi_e4 * lo_e5 (full k32)
        #pragma unroll
        for (int mi = 0; mi < 4; ++mi)
            #pragma unroll
            for (int nj = 0; nj < 4; ++nj)
                mma_f8_45(acc[mi][nj], A8h[mi], B8l[nj]);

        // fp8 set 2: A lo_e5 + B hi_e4
        uint32_t A8l[4][4], B8h[4][2];
        #pragma unroll
        for (int mi = 0; mi < 4; ++mi)
            ldsm4(A8l[mi], sb + 20480 + f8_off(wm + 16 * mi + r8, c8));
        #pragma unroll
        for (int jp = 0; jp < 2; ++jp) {
            uint32_t t[4];
            ldsm4(t, sb + 24576 + f8_off(wn + 16 * jp + r8, c8));
            B8h[2*jp][0] = t[0]; B8h[2*jp][1] = t[2];
            B8h[2*jp+1][0] = t[1]; B8h[2*jp+1][1] = t[3];
        }

        // pass 3: hi*hi kk1
        #pragma unroll
        for (int mi = 0; mi < 4; ++mi)
            #pragma unroll
            for (int nj = 0; nj < 4; ++nj)
                mma_bf16(acc[mi][nj], Ah1[mi], Bh1[nj]);

        // pass 4: cross lo_e5 * hi_e4 (full k32)
        #pragma unroll
        for (int mi = 0; mi < 4; ++mi)
            #pragma unroll
            for (int nj = 0; nj < 4; ++nj)
                mma_f8_54(acc[mi][nj], A8l[mi], B8h[nj]);
    }

    // ---- epilogue ----
    if constexpr (FIRST) {
        const int e = nBlk >> 9;
        float bcol[8];
        #pragma unroll
        for (int nj = 0; nj < 4; ++nj) {
            const int col = nBlk + wn + 8 * nj + 2 * (lane & 3);
            const int bc = e * HID_DIM + (col & (HID_DIM - 1));
            bcol[2*nj]   = bias[bc];
            bcol[2*nj+1] = bias[bc + 1];
        }
        #pragma unroll
        for (int mi = 0; mi < 4; ++mi)
            #pragma unroll
            for (int h = 0; h < 2; ++h) {
                const int row = mBlk + wm + 16 * mi + (lane >> 2) + 8 * h;
                const float g = gate[(size_t)row * N_EXP + e];
                #pragma unroll
                for (int nj = 0; nj < 4; ++nj) {
                    const int col = nBlk + wn + 8 * nj + 2 * (lane & 3);
                    float v0 = acc[mi][nj][2*h]   + bcol[2*nj];
                    float v1 = acc[mi][nj][2*h+1] + bcol[2*nj+1];
                    v0 = fmaxf(v0, 0.f) * g;
                    v1 = fmaxf(v1, 0.f) * g;
                    __nv_bfloat16 h0 = __float2bfloat16(v0);
                    __nv_bfloat16 h1 = __float2bfloat16(v1);
                    float l0 = v0 - __bfloat162float(h0);
                    float l1 = v1 - __bfloat162float(h1);
                    uint32_t ph = (uint32_t)__bfloat16_as_ushort(h0) | ((uint32_t)__bfloat16_as_ushort(h1) << 16);
                    *reinterpret_cast<uint32_t*>(Chi + (size_t)row * H3 + col) = ph;
                    *reinterpret_cast<uint16_t*>(Ch8 + (size_t)row * H3 + col) = pk_e4m3(v1, v0);
                    *reinterpret_cast<uint16_t*>(Cl8 + (size_t)row * H3 + col) = pk_e5m2(l1, l0);
                }
            }
    } else {
        float bb[8][N_EXP];
        #pragma unroll
        for (int nj = 0; nj < 4; ++nj) {
            const int col = nBlk + wn + 8 * nj + 2 * (lane & 3);
            #pragma unroll
            for (int q = 0; q < N_EXP; ++q) {
                bb[2*nj][q]   = bias[q * OUT_DIM + col];
                bb[2*nj+1][q] = bias[q * OUT_DIM + col + 1];
            }
        }
        #pragma unroll
        for (int mi = 0; mi < 4; ++mi)
            #pragma unroll
            for (int h = 0; h < 2; ++h) {
                const int row = mBlk + wm + 16 * mi + (lane >> 2) + 8 * h;
                const float2* gp = reinterpret_cast<const float2*>(gate + (size_t)row * N_EXP);
                float2 gA = gp[0], gB = gp[1], gC = gp[2];
                float gw[N_EXP] = {gA.x, gA.y, gB.x, gB.y, gC.x, gC.y};
                #pragma unroll
                for (int nj = 0; nj < 4; ++nj) {
                    const int col = nBlk + wn + 8 * nj + 2 * (lane & 3);
                    float v0 = acc[mi][nj][2*h];
                    float v1 = acc[mi][nj][2*h+1];
                    #pragma unroll
                    for (int q = 0; q < N_EXP; ++q) {
                        v0 = fmaf(gw[q], bb[2*nj][q],   v0);
                        v1 = fmaf(gw[q], bb[2*nj+1][q], v1);
                    }
                    *reinterpret_cast<float2*>(Cf + (size_t)row * OUT_DIM + col) = make_float2(v0, v1);
                }
            }
    }
}

// ---------------------------------------------------------------------------
extern "C" void kernel_launch(void* const* d_in, const int* in_sizes, int n_in,
                              void* d_out, int out_size)
{
    const float* x   = (const float*)d_in[0];
    const float* g2w = (const float*)d_in[1];
    const float* g2b = (const float*)d_in[2];
    const float* g3w = (const float*)d_in[3];
    const float* g3b = (const float*)d_in[4];
    const float* w1  = (const float*)d_in[5];
    const float* b1  = (const float*)d_in[6];
    const float* w2  = (const float*)d_in[7];
    const float* b2  = (const float*)d_in[8];
    float* out = (float*)d_out;

    const int B = in_sizes[0] / IN_DIM;   // 32768

    float* gate;
    __nv_bfloat16 *xhi, *w1hi, *w2hi, *hshi;
    uint8_t *xh8, *xl8, *w1h8, *w1l8, *w2h8, *w2l8, *hsh8, *hsl8;
    cudaGetSymbolAddress((void**)&gate, g_gate);
    cudaGetSymbolAddress((void**)&xhi, g_xhi);
    cudaGetSymbolAddress((void**)&xh8, g_xh8);
    cudaGetSymbolAddress((void**)&xl8, g_xl8);
    cudaGetSymbolAddress((void**)&w1hi, g_w1hi);
    cudaGetSymbolAddress((void**)&w1h8, g_w1h8);
    cudaGetSymbolAddress((void**)&w1l8, g_w1l8);
    cudaGetSymbolAddress((void**)&w2hi, g_w2hi);
    cudaGetSymbolAddress((void**)&w2h8, g_w2h8);
    cudaGetSymbolAddress((void**)&w2l8, g_w2l8);
    cudaGetSymbolAddress((void**)&hshi, g_hshi);
    cudaGetSymbolAddress((void**)&hsh8, g_hsh8);
    cudaGetSymbolAddress((void**)&hsl8, g_hsl8);

    cudaFuncSetAttribute(gemm_mma<IN_DIM, true>,
                         cudaFuncAttributeMaxDynamicSharedMemorySize, SMEM_TOTAL);
    cudaFuncSetAttribute(gemm_mma<H3, false>,
                         cudaFuncAttributeMaxDynamicSharedMemorySize, SMEM_TOTAL);

    // 1) gate + split x
    gate_split_kernel<<<(B + 7) / 8, 256>>>(x, g2w, g2b, g3w, g3b, gate, xhi, xh8, xl8, B);

    // 2) transpose+split weights
    transplit_kernel<<<dim3(HID_DIM/32, IN_DIM/32, N_EXP), dim3(32, 8)>>>(w1, w1hi, w1h8, w1l8, IN_DIM, HID_DIM);
    transplit_kernel<<<dim3(OUT_DIM/32, H3/32, 1),        dim3(32, 8)>>>(w2, w2hi, w2h8, w2l8, H3, OUT_DIM);

    // 3) hs = split(relu(x @ W1 + b1) * gate)   [B,3072] bf16 + fp8
    gemm_mma<IN_DIM, true><<<dim3(H3/BN, B/BM), 256, SMEM_TOTAL>>>(
        xhi, xh8, xl8, w1hi, w1h8, w1l8, b1, gate, hshi, hsh8, hsl8, nullptr);

    // 4) out = hs @ W2 + gate @ b2              [B,1024] fp32
    gemm_mma<H3, false><<<dim3(OUT_DIM/BN, B/BM), 256, SMEM_TOTAL>>>(
        hshi, hsh8, hsl8, w2hi, w2h8, w2l8, b2, gate, nullptr, nullptr, nullptr, out);
}

// round 9
// speedup vs baseline: 1.5949x; 1.5949x over previous
#include <cuda_runtime.h>
#include <cuda_fp16.h>
#include <cstdint>
#include <cstddef>

#define IN_DIM   1024
#define HID_DIM  512
#define OUT_DIM  1024
#define N_EXP    6
#define H3       3072
#define MAXB     32768

// ---------------- scratch (device globals; no allocation allowed) ----------
__device__ float  g_gate[(size_t)MAXB * N_EXP];
__device__ __half g_xhi [(size_t)MAXB * IN_DIM];
__device__ __half g_xlo [(size_t)MAXB * IN_DIM];
__device__ __half g_w1hi[(size_t)H3 * IN_DIM];     // [3072,1024] N-major, K contig
__device__ __half g_w1lo[(size_t)H3 * IN_DIM];
__device__ __half g_w2hi[(size_t)OUT_DIM * H3];    // [1024,3072]
__device__ __half g_w2lo[(size_t)OUT_DIM * H3];
__device__ __half g_hs  [(size_t)MAXB * H3];       // fp16 hidden (no residual stream)

// ---------------- helpers ---------------------------------------------------
__device__ __forceinline__ uint32_t smem_u32(const void* p) {
    uint32_t a;
    asm("{ .reg .u64 t; cvta.to.shared.u64 t, %1; cvt.u32.u64 %0, t; }" : "=r"(a) : "l"(p));
    return a;
}
__device__ __forceinline__ void cp16(uint32_t dst, const void* src) {
    asm volatile("cp.async.cg.shared.global [%0], [%1], 16;" :: "r"(dst), "l"(src));
}
__device__ __forceinline__ void cp_commit() {
    asm volatile("cp.async.commit_group;" ::: "memory");
}
template <int N>
__device__ __forceinline__ void cp_wait() {
    asm volatile("cp.async.wait_group %0;" :: "n"(N) : "memory");
}
__device__ __forceinline__ void ldsm4(uint32_t* r, uint32_t addr) {
    asm volatile("ldmatrix.sync.aligned.m8n8.x4.shared.b16 {%0,%1,%2,%3}, [%4];"
                 : "=r"(r[0]), "=r"(r[1]), "=r"(r[2]), "=r"(r[3]) : "r"(addr));
}
__device__ __forceinline__ void mma_f16(float* c, const uint32_t* a, const uint32_t* b) {
    asm volatile(
        "mma.sync.aligned.m16n8k16.row.col.f32.f16.f16.f32 "
        "{%0,%1,%2,%3}, {%4,%5,%6,%7}, {%8,%9}, {%0,%1,%2,%3};"
        : "+f"(c[0]), "+f"(c[1]), "+f"(c[2]), "+f"(c[3])
        : "r"(a[0]), "r"(a[1]), "r"(a[2]), "r"(a[3]), "r"(b[0]), "r"(b[1]));
}
// 64B rows, 16B chunks, xor-swizzle (conflict-free ldmatrix)
__device__ __forceinline__ int sw_off(int row, int chunk) {
    return row * 64 + ((chunk ^ ((row >> 1) & 3)) << 4);
}
__device__ __forceinline__ uint32_t pk_h2(float v0, float v1) {
    __half2 h = __halves2half2(__float2half_rn(v0), __float2half_rn(v1));
    return *reinterpret_cast<uint32_t*>(&h);
}

// ---------------- fused gate + x split (one pass over x) -------------------
__global__ __launch_bounds__(256) void gate_split_kernel(
    const float* __restrict__ x,
    const float* __restrict__ g2w, const float* __restrict__ g2b,
    const float* __restrict__ g3w, const float* __restrict__ g3b,
    float* __restrict__ gate,
    __half* __restrict__ xhi, __half* __restrict__ xlo, int B)
{
    int row  = (blockIdx.x * 256 + threadIdx.x) >> 5;
    int lane = threadIdx.x & 31;
    if (row >= B) return;

    const float4* xr = reinterpret_cast<const float4*>(x + (size_t)row * IN_DIM);
    float a0 = 0.f, a1 = 0.f, a2 = 0.f, a3 = 0.f;
    #pragma unroll
    for (int j = 0; j < 8; ++j) {
        int i = lane + j * 32;
        float4 v = xr[i];
        int k = i * 4;
        a0 = fmaf(v.x, g2w[k], fmaf(v.y, g2w[k+1], fmaf(v.z, g2w[k+2], fmaf(v.w, g2w[k+3], a0))));
        a1 = fmaf(v.x, g3w[k*3+0], fmaf(v.y, g3w[(k+1)*3+0], fmaf(v.z, g3w[(k+2)*3+0], fmaf(v.w, g3w[(k+3)*3+0], a1))));
        a2 = fmaf(v.x, g3w[k*3+1], fmaf(v.y, g3w[(k+1)*3+1], fmaf(v.z, g3w[(k+2)*3+1], fmaf(v.w, g3w[(k+3)*3+1], a2))));
        a3 = fmaf(v.x, g3w[k*3+2], fmaf(v.y, g3w[(k+1)*3+2], fmaf(v.z, g3w[(k+2)*3+2], fmaf(v.w, g3w[(k+3)*3+2], a3))));
        float vv[4] = {v.x, v.y, v.z, v.w};
        uint32_t ph[2], pl[2];
        #pragma unroll
        for (int q = 0; q < 2; ++q) {
            float u0 = vv[2*q], u1 = vv[2*q+1];
            __half h0 = __float2half_rn(u0);
            __half h1 = __float2half_rn(u1);
            float l0 = u0 - __half2float(h0);
            float l1 = u1 - __half2float(h1);
            __half2 hp = __halves2half2(h0, h1);
            __half2 lp = __halves2half2(__float2half_rn(l0), __float2half_rn(l1));
            ph[q] = *reinterpret_cast<uint32_t*>(&hp);
            pl[q] = *reinterpret_cast<uint32_t*>(&lp);
        }
        *reinterpret_cast<uint2*>(xhi + (size_t)row * IN_DIM + k) = make_uint2(ph[0], ph[1]);
        *reinterpret_cast<uint2*>(xlo + (size_t)row * IN_DIM + k) = make_uint2(pl[0], pl[1]);
    }
    #pragma unroll
    for (int off = 16; off > 0; off >>= 1) {
        a0 += __shfl_down_sync(0xffffffffu, a0, off);
        a1 += __shfl_down_sync(0xffffffffu, a1, off);
        a2 += __shfl_down_sync(0xffffffffu, a2, off);
        a3 += __shfl_down_sync(0xffffffffu, a3, off);
    }
    if (lane == 0) {
        float alpha = 1.f / (1.f + expf(-(a0 + g2b[0])));
        float l0 = a1 + g3b[0], l1 = a2 + g3b[1], l2 = a3 + g3b[2];
        float m = fmaxf(l0, fmaxf(l1, l2));
        float e0 = expf(l0 - m), e1 = expf(l1 - m), e2 = expf(l2 - m);
        float inv = 1.f / (e0 + e1 + e2);
        float p0 = e0 * inv, p1 = e1 * inv, p2 = e2 * inv, ga = 1.f - alpha;
        float* o = gate + (size_t)row * N_EXP;
        o[0] = ga * p0;    o[1] = ga * p1;    o[2] = ga * p2;
        o[3] = alpha * p0; o[4] = alpha * p1; o[5] = alpha * p2;
    }
}

// ---------------- transpose + split: src[R,C] fp32 -> dst[C,R] fp16 hi/lo --
__global__ void transplit_kernel(const float* __restrict__ src,
                                 __half* __restrict__ dhi,
                                 __half* __restrict__ dlo, int R, int C)
{
    __shared__ float t[32][33];
    size_t zoff = (size_t)blockIdx.z * R * C;
    int c0 = blockIdx.x * 32, r0 = blockIdx.y * 32;
    int tx = threadIdx.x, ty = threadIdx.y;          // 32 x 8
    #pragma unroll
    for (int i = 0; i < 4; ++i)
        t[ty + i*8][tx] = src[zoff + (size_t)(r0 + ty + i*8) * C + c0 + tx];
    __syncthreads();
    #pragma unroll
    for (int i = 0; i < 4; ++i) {
        int c = c0 + ty + i*8, r = r0 + tx;
        float v = t[tx][ty + i*8];
        __half h = __float2half_rn(v);
        float l = v - __half2float(h);
        dhi[zoff + (size_t)c * R + r] = h;
        dlo[zoff + (size_t)c * R + r] = __float2half_rn(l);
    }
}

// ================== GEMM1: 3-pass fp16 split ================================
// CTA 128x128, BK=32, 8 warps (2Mx4N), warp 64x32, fp32 acc.
// acc += Ahi*Bhi + Ahi*Blo + Alo*Bhi. hs written as fp16 (single stream).
#define BM 128
#define BN 128
#define BK 32
#define STAGES1 3
#define STAGE1_BYTES 32768   // Ahi 8K | Alo 8K | Bhi 8K | Blo 8K
#define SMEM1_TOTAL (STAGES1 * STAGE1_BYTES)

__global__ __launch_bounds__(256, 2) void gemm1_mma(
    const __half* __restrict__ Ahi, const __half* __restrict__ Alo,
    const __half* __restrict__ Bhi, const __half* __restrict__ Blo,
    const float* __restrict__ bias, const float* __restrict__ gate,
    __half* __restrict__ Chs)
{
    extern __shared__ char smem[];
    const uint32_t sbase = smem_u32(smem);
    const int tid  = threadIdx.x;
    const int wid  = tid >> 5;
    const int lane = tid & 31;
    const int mBlk = blockIdx.y * BM;
    const int nBlk = blockIdx.x * BN;
    const int wm = (wid >> 2) * 64;
    const int wn = (wid & 3) * 32;
    constexpr int K = IN_DIM;
    constexpr int NK = K / BK;

    const __half* srcTab[4];
    srcTab[0] = Ahi + (size_t)mBlk * K;
    srcTab[1] = Alo + (size_t)mBlk * K;
    srcTab[2] = Bhi + (size_t)nBlk * K;
    srcTab[3] = Blo + (size_t)nBlk * K;

    float acc[4][4][4];
    #pragma unroll
    for (int i = 0; i < 4; ++i)
        #pragma unroll
        for (int j = 0; j < 4; ++j)
            #pragma unroll
            for (int q = 0; q < 4; ++q) acc[i][j][q] = 0.f;

    auto load_stage = [&](int s) {
        const int k0 = s * BK;
        const uint32_t sb = sbase + (s % STAGES1) * STAGE1_BYTES;
        #pragma unroll
        for (int j = 0; j < 8; ++j) {
            int idx = tid + (j & 3) * 256;
            int reg = (j >> 2) * 2 + (idx >> 9);
            int row = (idx >> 2) & 127;
            int c   = idx & 3;
            cp16(sb + reg * 8192 + sw_off(row, c),
                 srcTab[reg] + (size_t)row * K + k0 + c * 8);
        }
        cp_commit();
    };

    #pragma unroll
    for (int s = 0; s < STAGES1 - 1; ++s) load_stage(s);

    const int rA = wm + (lane & 15);
    const int rB = wn + ((lane >> 4) << 3) + (lane & 7);
    const int cAoff = lane >> 4;
    const int cBoff = (lane >> 3) & 1;

    #pragma unroll 3
    for (int s = 0; s < NK; ++s) {
        cp_wait<STAGES1 - 2>();
        __syncthreads();
        const uint32_t sb = sbase + (s % STAGES1) * STAGE1_BYTES;

        uint32_t Ah[4][4], Bh[4][2];
        #pragma unroll
        for (int mi = 0; mi < 4; ++mi)
            ldsm4(Ah[mi], sb + sw_off(rA + 16 * mi, cAoff));
        #pragma unroll
        for (int jp = 0; jp < 2; ++jp) {
            uint32_t t[4];
            ldsm4(t, sb + 16384 + sw_off(rB + 16 * jp, cBoff));
            Bh[2*jp][0] = t[0]; Bh[2*jp][1] = t[1];
            Bh[2*jp+1][0] = t[2]; Bh[2*jp+1][1] = t[3];
        }

        if (s + STAGES1 - 1 < NK) load_stage(s + STAGES1 - 1);
        else cp_commit();

        #pragma unroll
        for (int kk = 0; kk < 2; ++kk) {
            const int c = kk * 2;
            // pass 1: hi*hi
            #pragma unroll
            for (int mi = 0; mi < 4; ++mi)
                #pragma unroll
                for (int nj = 0; nj < 4; ++nj)
                    mma_f16(acc[mi][nj], Ah[mi], Bh[nj]);
            // pass 2: hi*lo
            uint32_t Bl[4][2];
            #pragma unroll
            for (int jp = 0; jp < 2; ++jp) {
                uint32_t t[4];
                ldsm4(t, sb + 24576 + sw_off(rB + 16 * jp, c + cBoff));
                Bl[2*jp][0] = t[0]; Bl[2*jp][1] = t[1];
                Bl[2*jp+1][0] = t[2]; Bl[2*jp+1][1] = t[3];
            }
            #pragma unroll
            for (int mi = 0; mi < 4; ++mi)
                #pragma unroll
                for (int nj = 0; nj < 4; ++nj)
                    mma_f16(acc[mi][nj], Ah[mi], Bl[nj]);
            // Ah dead -> prefetch Ah(kk1); pass 3: lo*hi
            uint32_t Al[4][4];
            #pragma unroll
            for (int mi = 0; mi < 4; ++mi)
                ldsm4(Al[mi], sb + 8192 + sw_off(rA + 16 * mi, c + cAoff));
            if (kk == 0) {
                #pragma unroll
                for (int mi = 0; mi < 4; ++mi)
                    ldsm4(Ah[mi], sb + sw_off(rA + 16 * mi, 2 + cAoff));
            }
            #pragma unroll
            for (int mi = 0; mi < 4; ++mi)
                #pragma unroll
                for (int nj = 0; nj < 4; ++nj)
                    mma_f16(acc[mi][nj], Al[mi], Bh[nj]);
            if (kk == 0) {
                #pragma unroll
                for (int jp = 0; jp < 2; ++jp) {
                    uint32_t t[4];
                    ldsm4(t, sb + 16384 + sw_off(rB + 16 * jp, 2 + cBoff));
                    Bh[2*jp][0] = t[0]; Bh[2*jp][1] = t[1];
                    Bh[2*jp+1][0] = t[2]; Bh[2*jp+1][1] = t[3];
                }
            }
        }
    }

    // epilogue: hs = fp16(relu(acc + b1) * gate)
    const int e = nBlk >> 9;
    float bcol[8];
    #pragma unroll
    for (int nj = 0; nj < 4; ++nj) {
        const int col = nBlk + wn + 8 * nj + 2 * (lane & 3);
        const int bc = e * HID_DIM + (col & (HID_DIM - 1));
        bcol[2*nj]   = bias[bc];
        bcol[2*nj+1] = bias[bc + 1];
    }
    #pragma unroll
    for (int mi = 0; mi < 4; ++mi)
        #pragma unroll
        for (int h = 0; h < 2; ++h) {
            const int row = mBlk + wm + 16 * mi + (lane >> 2) + 8 * h;
            const float g = gate[(size_t)row * N_EXP + e];
            #pragma unroll
            for (int nj = 0; nj < 4; ++nj) {
                const int col = nBlk + wn + 8 * nj + 2 * (lane & 3);
                float v0 = fmaxf(acc[mi][nj][2*h]   + bcol[2*nj],   0.f) * g;
                float v1 = fmaxf(acc[mi][nj][2*h+1] + bcol[2*nj+1], 0.f) * g;
                *reinterpret_cast<uint32_t*>(Chs + (size_t)row * H3 + col) = pk_h2(v0, v1);
            }
        }
}

// ================== GEMM2: 2-pass (hs fp16) x (W2 fp16 hi/lo) ===============
// CTA 128x128, BK=32, 8 warps, warp 64x32, fp32 acc, 4-stage pipeline.
// acc += A*Bhi + A*Blo.  out = acc + gate@b2 (fp32).
#define STAGES2 4
#define STAGE2_BYTES 24576   // A 8K | Bhi 8K | Blo 8K
#define SMEM2_TOTAL (STAGES2 * STAGE2_BYTES)

__global__ __launch_bounds__(256, 2) void gemm2_mma(
    const __half* __restrict__ A,
    const __half* __restrict__ Bhi, const __half* __restrict__ Blo,
    const float* __restrict__ bias, const float* __restrict__ gate,
    float* __restrict__ Cf)
{
    extern __shared__ char smem[];
    const uint32_t sbase = smem_u32(smem);
    const int tid  = threadIdx.x;
    const int wid  = tid >> 5;
    const int lane = tid & 31;
    const int mBlk = blockIdx.y * BM;
    const int nBlk = blockIdx.x * BN;
    const int wm = (wid >> 2) * 64;
    const int wn = (wid & 3) * 32;
    constexpr int K = H3;
    constexpr int NK = K / BK;

    const __half* srcTab[3];
    srcTab[0] = A   + (size_t)mBlk * K;
    srcTab[1] = Bhi + (size_t)nBlk * K;
    srcTab[2] = Blo + (size_t)nBlk * K;

    float acc[4][4][4];
    #pragma unroll
    for (int i = 0; i < 4; ++i)
        #pragma unroll
        for (int j = 0; j < 4; ++j)
            #pragma unroll
            for (int q = 0; q < 4; ++q) acc[i][j][q] = 0.f;

    auto load_stage = [&](int s) {
        const int k0 = s * BK;
        const uint32_t sb = sbase + (s % STAGES2) * STAGE2_BYTES;
        #pragma unroll
        for (int j = 0; j < 6; ++j) {
            int idx = tid + j * 256;          // 0..1535
            int reg = idx >> 9;               // 0=A,1=Bhi,2=Blo
            int i = idx & 511;
            int row = i >> 2, c = i & 3;
            cp16(sb + reg * 8192 + sw_off(row, c),
                 srcTab[reg] + (size_t)row * K + k0 + c * 8);
        }
        cp_commit();
    };

    #pragma unroll
    for (int s = 0; s < STAGES2 - 1; ++s) load_stage(s);

    const int rA = wm + (lane & 15);
    const int rB = wn + ((lane >> 4) << 3) + (lane & 7);
    const int cAoff = lane >> 4;
    const int cBoff = (lane >> 3) & 1;

    #pragma unroll 4
    for (int s = 0; s < NK; ++s) {
        cp_wait<STAGES2 - 2>();
        __syncthreads();
        const uint32_t sb = sbase + (s % STAGES2) * STAGE2_BYTES;

        uint32_t Ah[4][4], Bh[4][2];
        #pragma unroll
        for (int mi = 0; mi < 4; ++mi)
            ldsm4(Ah[mi], sb + sw_off(rA + 16 * mi, cAoff));
        #pragma unroll
        for (int jp = 0; jp < 2; ++jp) {
            uint32_t t[4];
            ldsm4(t, sb + 8192 + sw_off(rB + 16 * jp, cBoff));
            Bh[2*jp][0] = t[0]; Bh[2*jp][1] = t[1];
            Bh[2*jp+1][0] = t[2]; Bh[2*jp+1][1] = t[3];
        }

        if (s + STAGES2 - 1 < NK) load_stage(s + STAGES2 - 1);
        else cp_commit();

        #pragma unroll
        for (int kk = 0; kk < 2; ++kk) {
            const int c = kk * 2;
            // pass 1: A*Bhi
            #pragma unroll
            for (int mi = 0; mi < 4; ++mi)
                #pragma unroll
                for (int nj = 0; nj < 4; ++nj)
                    mma_f16(acc[mi][nj], Ah[mi], Bh[nj]);
            // pass 2: A*Blo
            uint32_t Bl[4][2];
            #pragma unroll
            for (int jp = 0; jp < 2; ++jp) {
                uint32_t t[4];
                ldsm4(t, sb + 16384 + sw_off(rB + 16 * jp, c + cBoff));
                Bl[2*jp][0] = t[0]; Bl[2*jp][1] = t[1];
                Bl[2*jp+1][0] = t[2]; Bl[2*jp+1][1] = t[3];
            }
            #pragma unroll
            for (int mi = 0; mi < 4; ++mi)
                #pragma unroll
                for (int nj = 0; nj < 4; ++nj)
                    mma_f16(acc[mi][nj], Ah[mi], Bl[nj]);
            // prefetch kk1 frags under pass-2 tail
            if (kk == 0) {
                #pragma unroll
                for (int mi = 0; mi < 4; ++mi)
                    ldsm4(Ah[mi], sb + sw_off(rA + 16 * mi, 2 + cAoff));
                #pragma unroll
                for (int jp = 0; jp < 2; ++jp) {
                    uint32_t t[4];
                    ldsm4(t, sb + 8192 + sw_off(rB + 16 * jp, 2 + cBoff));
                    Bh[2*jp][0] = t[0]; Bh[2*jp][1] = t[1];
                    Bh[2*jp+1][0] = t[2]; Bh[2*jp+1][1] = t[3];
                }
            }
        }
    }

    // epilogue: out = acc + gate @ b2
    float bb[8][N_EXP];
    #pragma unroll
    for (int nj = 0; nj < 4; ++nj) {
        const int col = nBlk + wn + 8 * nj + 2 * (lane & 3);
        #pragma unroll
        for (int q = 0; q < N_EXP; ++q) {
            bb[2*nj][q]   = bias[q * OUT_DIM + col];
            bb[2*nj+1][q] = bias[q * OUT_DIM + col + 1];
        }
    }
    #pragma unroll
    for (int mi = 0; mi < 4; ++mi)
        #pragma unroll
        for (int h = 0; h < 2; ++h) {
            const int row = mBlk + wm + 16 * mi + (lane >> 2) + 8 * h;
            const float2* gp = reinterpret_cast<const float2*>(gate + (size_t)row * N_EXP);
            float2 gA = gp[0], gB = gp[1], gC = gp[2];
            float gw[N_EXP] = {gA.x, gA.y, gB.x, gB.y, gC.x, gC.y};
            #pragma unroll
            for (int nj = 0; nj < 4; ++nj) {
                const int col = nBlk + wn + 8 * nj + 2 * (lane & 3);
                float v0 = acc[mi][nj][2*h];
                float v1 = acc[mi][nj][2*h+1];
                #pragma unroll
                for (int q = 0; q < N_EXP; ++q) {
                    v0 = fmaf(gw[q], bb[2*nj][q],   v0);
                    v1 = fmaf(gw[q], bb[2*nj+1][q], v1);
                }
                *reinterpret_cast<float2*>(Cf + (size_t)row * OUT_DIM + col) = make_float2(v0, v1);
            }
        }
}

// ---------------------------------------------------------------------------
extern "C" void kernel_launch(void* const* d_in, const int* in_sizes, int n_in,
                              void* d_out, int out_size)
{
    const float* x   = (const float*)d_in[0];
    const float* g2w = (const float*)d_in[1];
    const float* g2b = (const float*)d_in[2];
    const float* g3w = (const float*)d_in[3];
    const float* g3b = (const float*)d_in[4];
    const float* w1  = (const float*)d_in[5];
    const float* b1  = (const float*)d_in[6];
    const float* w2  = (const float*)d_in[7];
    const float* b2  = (const float*)d_in[8];
    float* out = (float*)d_out;

    const int B = in_sizes[0] / IN_DIM;   // 32768

    float* gate;
    __half *xhi, *xlo, *w1hi, *w1lo, *w2hi, *w2lo, *hs;
    cudaGetSymbolAddress((void**)&gate, g_gate);
    cudaGetSymbolAddress((void**)&xhi, g_xhi);
    cudaGetSymbolAddress((void**)&xlo, g_xlo);
    cudaGetSymbolAddress((void**)&w1hi, g_w1hi);
    cudaGetSymbolAddress((void**)&w1lo, g_w1lo);
    cudaGetSymbolAddress((void**)&w2hi, g_w2hi);
    cudaGetSymbolAddress((void**)&w2lo, g_w2lo);
    cudaGetSymbolAddress((void**)&hs, g_hs);

    cudaFuncSetAttribute(gemm1_mma, cudaFuncAttributeMaxDynamicSharedMemorySize, SMEM1_TOTAL);
    cudaFuncSetAttribute(gemm2_mma, cudaFuncAttributeMaxDynamicSharedMemorySize, SMEM2_TOTAL);

    // 1) gate + split x (fp16 hi/lo)
    gate_split_kernel<<<(B + 7) / 8, 256>>>(x, g2w, g2b, g3w, g3b, gate, xhi, xlo, B);

    // 2) transpose+split weights (fp16 hi/lo)
    transplit_kernel<<<dim3(HID_DIM/32, IN_DIM/32, N_EXP), dim3(32, 8)>>>(w1, w1hi, w1lo, IN_DIM, HID_DIM);
    transplit_kernel<<<dim3(OUT_DIM/32, H3/32, 1),        dim3(32, 8)>>>(w2, w2hi, w2lo, H3, OUT_DIM);

    // 3) hs = fp16(relu(x @ W1 + b1) * gate)   [B,3072]  (3-pass fp16 split)
    gemm1_mma<<<dim3(H3/BN, B/BM), 256, SMEM1_TOTAL>>>(
        xhi, xlo, w1hi, w1lo, b1, gate, hs);

    // 4) out = hs @ W2 + gate @ b2             [B,1024]  (2-pass: W2 hi+lo)
    gemm2_mma<<<dim3(OUT_DIM/BN, B/BM), 256, SMEM2_TOTAL>>>(
        hs, w2hi, w2lo, b2, gate, out);
}

// round 10
// speedup vs baseline: 2.0130x; 1.2622x over previous
#include <cuda_runtime.h>
#include <cuda_fp16.h>
#include <cstdint>
#include <cstddef>

#define IN_DIM   1024
#define HID_DIM  512
#define OUT_DIM  1024
#define N_EXP    6
#define H3       3072
#define MAXB     32768

// ---------------- scratch (device globals; no allocation allowed) ----------
__device__ float  g_gate[(size_t)MAXB * N_EXP];
__device__ __half g_xh  [(size_t)MAXB * IN_DIM];   // fp16(x), single stream
__device__ __half g_w1hi[(size_t)H3 * IN_DIM];     // [3072,1024] N-major, K contig
__device__ __half g_w1lo[(size_t)H3 * IN_DIM];
__device__ __half g_w2hi[(size_t)OUT_DIM * H3];    // [1024,3072]
__device__ __half g_w2lo[(size_t)OUT_DIM * H3];
__device__ __half g_hs  [(size_t)MAXB * H3];       // fp16 hidden, single stream

// ---------------- helpers ---------------------------------------------------
__device__ __forceinline__ uint32_t smem_u32(const void* p) {
    uint32_t a;
    asm("{ .reg .u64 t; cvta.to.shared.u64 t, %1; cvt.u32.u64 %0, t; }" : "=r"(a) : "l"(p));
    return a;
}
__device__ __forceinline__ void cp16(uint32_t dst, const void* src) {
    asm volatile("cp.async.cg.shared.global [%0], [%1], 16;" :: "r"(dst), "l"(src));
}
__device__ __forceinline__ void cp_commit() {
    asm volatile("cp.async.commit_group;" ::: "memory");
}
template <int N>
__device__ __forceinline__ void cp_wait() {
    asm volatile("cp.async.wait_group %0;" :: "n"(N) : "memory");
}
__device__ __forceinline__ void ldsm4(uint32_t* r, uint32_t addr) {
    asm volatile("ldmatrix.sync.aligned.m8n8.x4.shared.b16 {%0,%1,%2,%3}, [%4];"
                 : "=r"(r[0]), "=r"(r[1]), "=r"(r[2]), "=r"(r[3]) : "r"(addr));
}
__device__ __forceinline__ void mma_f16(float* c, const uint32_t* a, const uint32_t* b) {
    asm volatile(
        "mma.sync.aligned.m16n8k16.row.col.f32.f16.f16.f32 "
        "{%0,%1,%2,%3}, {%4,%5,%6,%7}, {%8,%9}, {%0,%1,%2,%3};"
        : "+f"(c[0]), "+f"(c[1]), "+f"(c[2]), "+f"(c[3])
        : "r"(a[0]), "r"(a[1]), "r"(a[2]), "r"(a[3]), "r"(b[0]), "r"(b[1]));
}
// 64B rows, 16B chunks, xor-swizzle (conflict-free ldmatrix)
__device__ __forceinline__ int sw_off(int row, int chunk) {
    return row * 64 + ((chunk ^ ((row >> 1) & 3)) << 4);
}
__device__ __forceinline__ uint32_t pk_h2(float v0, float v1) {
    __half2 h = __halves2half2(__float2half_rn(v0), __float2half_rn(v1));
    return *reinterpret_cast<uint32_t*>(&h);
}

// ---------------- fused gate + fp16 quantize of x ---------------------------
__global__ __launch_bounds__(256) void gate_split_kernel(
    const float* __restrict__ x,
    const float* __restrict__ g2w, const float* __restrict__ g2b,
    const float* __restrict__ g3w, const float* __restrict__ g3b,
    float* __restrict__ gate, __half* __restrict__ xh, int B)
{
    int row  = (blockIdx.x * 256 + threadIdx.x) >> 5;
    int lane = threadIdx.x & 31;
    if (row >= B) return;

    const float4* xr = reinterpret_cast<const float4*>(x + (size_t)row * IN_DIM);
    float a0 = 0.f, a1 = 0.f, a2 = 0.f, a3 = 0.f;
    #pragma unroll
    for (int j = 0; j < 8; ++j) {
        int i = lane + j * 32;
        float4 v = xr[i];
        int k = i * 4;
        a0 = fmaf(v.x, g2w[k], fmaf(v.y, g2w[k+1], fmaf(v.z, g2w[k+2], fmaf(v.w, g2w[k+3], a0))));
        a1 = fmaf(v.x, g3w[k*3+0], fmaf(v.y, g3w[(k+1)*3+0], fmaf(v.z, g3w[(k+2)*3+0], fmaf(v.w, g3w[(k+3)*3+0], a1))));
        a2 = fmaf(v.x, g3w[k*3+1], fmaf(v.y, g3w[(k+1)*3+1], fmaf(v.z, g3w[(k+2)*3+1], fmaf(v.w, g3w[(k+3)*3+1], a2))));
        a3 = fmaf(v.x, g3w[k*3+2], fmaf(v.y, g3w[(k+1)*3+2], fmaf(v.z, g3w[(k+2)*3+2], fmaf(v.w, g3w[(k+3)*3+2], a3))));
        *reinterpret_cast<uint2*>(xh + (size_t)row * IN_DIM + k) =
            make_uint2(pk_h2(v.x, v.y), pk_h2(v.z, v.w));
    }
    #pragma unroll
    for (int off = 16; off > 0; off >>= 1) {
        a0 += __shfl_down_sync(0xffffffffu, a0, off);
        a1 += __shfl_down_sync(0xffffffffu, a1, off);
        a2 += __shfl_down_sync(0xffffffffu, a2, off);
        a3 += __shfl_down_sync(0xffffffffu, a3, off);
    }
    if (lane == 0) {
        float alpha = 1.f / (1.f + expf(-(a0 + g2b[0])));
        float l0 = a1 + g3b[0], l1 = a2 + g3b[1], l2 = a3 + g3b[2];
        float m = fmaxf(l0, fmaxf(l1, l2));
        float e0 = expf(l0 - m), e1 = expf(l1 - m), e2 = expf(l2 - m);
        float inv = 1.f / (e0 + e1 + e2);
        float p0 = e0 * inv, p1 = e1 * inv, p2 = e2 * inv, ga = 1.f - alpha;
        float* o = gate + (size_t)row * N_EXP;
        o[0] = ga * p0;    o[1] = ga * p1;    o[2] = ga * p2;
        o[3] = alpha * p0; o[4] = alpha * p1; o[5] = alpha * p2;
    }
}

// ---------------- transpose + split: src[R,C] fp32 -> dst[C,R] fp16 hi/lo --
__global__ void transplit_kernel(const float* __restrict__ src,
                                 __half* __restrict__ dhi,
                                 __half* __restrict__ dlo, int R, int C)
{
    __shared__ float t[32][33];
    size_t zoff = (size_t)blockIdx.z * R * C;
    int c0 = blockIdx.x * 32, r0 = blockIdx.y * 32;
    int tx = threadIdx.x, ty = threadIdx.y;          // 32 x 8
    #pragma unroll
    for (int i = 0; i < 4; ++i)
        t[ty + i*8][tx] = src[zoff + (size_t)(r0 + ty + i*8) * C + c0 + tx];
    __syncthreads();
    #pragma unroll
    for (int i = 0; i < 4; ++i) {
        int c = c0 + ty + i*8, r = r0 + tx;
        float v = t[tx][ty + i*8];
        __half h = __float2half_rn(v);
        float l = v - __half2float(h);
        dhi[zoff + (size_t)c * R + r] = h;
        dlo[zoff + (size_t)c * R + r] = __float2half_rn(l);
    }
}

// ================== unified 2-pass GEMM =====================================
// CTA 128x128, BK=32, 8 warps (2Mx4N), warp 64x32, fp32 acc, 4-stage pipeline.
// acc += A*Bhi + A*Blo   (A single fp16 stream; B = weight split hi/lo)
// FIRST epilogue: hs = fp16(relu(acc + b1) * gate)
// else:           out = acc + gate @ b2   (fp32)
#define BM 128
#define BN 128
#define BK 32
#define STAGES 4
#define STAGE_BYTES 24576   // A 8K | Bhi 8K | Blo 8K
#define SMEM_TOTAL (STAGES * STAGE_BYTES)

template <int K, bool FIRST>
__global__ __launch_bounds__(256, 2) void gemm_mma(
    const __half* __restrict__ A,
    const __half* __restrict__ Bhi, const __half* __restrict__ Blo,
    const float* __restrict__ bias, const float* __restrict__ gate,
    __half* __restrict__ Chs, float* __restrict__ Cf)
{
    extern __shared__ char smem[];
    const uint32_t sbase = smem_u32(smem);
    const int tid  = threadIdx.x;
    const int wid  = tid >> 5;
    const int lane = tid & 31;
    const int mBlk = blockIdx.y * BM;
    const int nBlk = blockIdx.x * BN;
    const int wm = (wid >> 2) * 64;
    const int wn = (wid & 3) * 32;
    constexpr int NK = K / BK;

    const __half* srcTab[3];
    srcTab[0] = A   + (size_t)mBlk * K;
    srcTab[1] = Bhi + (size_t)nBlk * K;
    srcTab[2] = Blo + (size_t)nBlk * K;

    float acc[4][4][4];
    #pragma unroll
    for (int i = 0; i < 4; ++i)
        #pragma unroll
        for (int j = 0; j < 4; ++j)
            #pragma unroll
            for (int q = 0; q < 4; ++q) acc[i][j][q] = 0.f;

    auto load_stage = [&](int s) {
        const int k0 = s * BK;
        const uint32_t sb = sbase + (s % STAGES) * STAGE_BYTES;
        #pragma unroll
        for (int j = 0; j < 6; ++j) {
            int idx = tid + j * 256;          // 0..1535
            int reg = idx >> 9;               // 0=A,1=Bhi,2=Blo
            int i = idx & 511;
            int row = i >> 2, c = i & 3;
            cp16(sb + reg * 8192 + sw_off(row, c),
                 srcTab[reg] + (size_t)row * K + k0 + c * 8);
        }
        cp_commit();
    };

    #pragma unroll
    for (int s = 0; s < STAGES - 1; ++s) load_stage(s);

    const int rA = wm + (lane & 15);
    const int rB = wn + ((lane >> 4) << 3) + (lane & 7);
    const int cAoff = lane >> 4;
    const int cBoff = (lane >> 3) & 1;

    #pragma unroll 4
    for (int s = 0; s < NK; ++s) {
        cp_wait<STAGES - 2>();
        __syncthreads();
        const uint32_t sb = sbase + (s % STAGES) * STAGE_BYTES;

        uint32_t Ah[4][4], Bh[4][2];
        #pragma unroll
        for (int mi = 0; mi < 4; ++mi)
            ldsm4(Ah[mi], sb + sw_off(rA + 16 * mi, cAoff));
        #pragma unroll
        for (int jp = 0; jp < 2; ++jp) {
            uint32_t t[4];
            ldsm4(t, sb + 8192 + sw_off(rB + 16 * jp, cBoff));
            Bh[2*jp][0] = t[0]; Bh[2*jp][1] = t[1];
            Bh[2*jp+1][0] = t[2]; Bh[2*jp+1][1] = t[3];
        }

        if (s + STAGES - 1 < NK) load_stage(s + STAGES - 1);
        else cp_commit();

        #pragma unroll
        for (int kk = 0; kk < 2; ++kk) {
            const int c = kk * 2;
            // pass 1: A*Bhi
            #pragma unroll
            for (int mi = 0; mi < 4; ++mi)
                #pragma unroll
                for (int nj = 0; nj < 4; ++nj)
                    mma_f16(acc[mi][nj], Ah[mi], Bh[nj]);
            // pass 2: A*Blo
            uint32_t Bl[4][2];
            #pragma unroll
            for (int jp = 0; jp < 2; ++jp) {
                uint32_t t[4];
                ldsm4(t, sb + 16384 + sw_off(rB + 16 * jp, c + cBoff));
                Bl[2*jp][0] = t[0]; Bl[2*jp][1] = t[1];
                Bl[2*jp+1][0] = t[2]; Bl[2*jp+1][1] = t[3];
            }
            #pragma unroll
            for (int mi = 0; mi < 4; ++mi)
                #pragma unroll
                for (int nj = 0; nj < 4; ++nj)
                    mma_f16(acc[mi][nj], Ah[mi], Bl[nj]);
            // prefetch kk1 frags under pass-2 tail
            if (kk == 0) {
                #pragma unroll
                for (int mi = 0; mi < 4; ++mi)
                    ldsm4(Ah[mi], sb + sw_off(rA + 16 * mi, 2 + cAoff));
                #pragma unroll
                for (int jp = 0; jp < 2; ++jp) {
                    uint32_t t[4];
                    ldsm4(t, sb + 8192 + sw_off(rB + 16 * jp, 2 + cBoff));
                    Bh[2*jp][0] = t[0]; Bh[2*jp][1] = t[1];
                    Bh[2*jp+1][0] = t[2]; Bh[2*jp+1][1] = t[3];
                }
            }
        }
    }

    // ---- epilogue ----
    if constexpr (FIRST) {
        const int e = nBlk >> 9;
        float bcol[8];
        #pragma unroll
        for (int nj = 0; nj < 4; ++nj) {
            const int col = nBlk + wn + 8 * nj + 2 * (lane & 3);
            const int bc = e * HID_DIM + (col & (HID_DIM - 1));
            bcol[2*nj]   = bias[bc];
            bcol[2*nj+1] = bias[bc + 1];
        }
        #pragma unroll
        for (int mi = 0; mi < 4; ++mi)
            #pragma unroll
            for (int h = 0; h < 2; ++h) {
                const int row = mBlk + wm + 16 * mi + (lane >> 2) + 8 * h;
                const float g = gate[(size_t)row * N_EXP + e];
                #pragma unroll
                for (int nj = 0; nj < 4; ++nj) {
                    const int col = nBlk + wn + 8 * nj + 2 * (lane & 3);
                    float v0 = fmaxf(acc[mi][nj][2*h]   + bcol[2*nj],   0.f) * g;
                    float v1 = fmaxf(acc[mi][nj][2*h+1] + bcol[2*nj+1], 0.f) * g;
                    *reinterpret_cast<uint32_t*>(Chs + (size_t)row * H3 + col) = pk_h2(v0, v1);
                }
            }
    } else {
        float bb[8][N_EXP];
        #pragma unroll
        for (int nj = 0; nj < 4; ++nj) {
            const int col = nBlk + wn + 8 * nj + 2 * (lane & 3);
            #pragma unroll
            for (int q = 0; q < N_EXP; ++q) {
                bb[2*nj][q]   = bias[q * OUT_DIM + col];
                bb[2*nj+1][q] = bias[q * OUT_DIM + col + 1];
            }
        }
        #pragma unroll
        for (int mi = 0; mi < 4; ++mi)
            #pragma unroll
            for (int h = 0; h < 2; ++h) {
                const int row = mBlk + wm + 16 * mi + (lane >> 2) + 8 * h;
                const float2* gp = reinterpret_cast<const float2*>(gate + (size_t)row * N_EXP);
                float2 gA = gp[0], gB = gp[1], gC = gp[2];
                float gw[N_EXP] = {gA.x, gA.y, gB.x, gB.y, gC.x, gC.y};
                #pragma unroll
                for (int nj = 0; nj < 4; ++nj) {
                    const int col = nBlk + wn + 8 * nj + 2 * (lane & 3);
                    float v0 = acc[mi][nj][2*h];
                    float v1 = acc[mi][nj][2*h+1];
                    #pragma unroll
                    for (int q = 0; q < N_EXP; ++q) {
                        v0 = fmaf(gw[q], bb[2*nj][q],   v0);
                        v1 = fmaf(gw[q], bb[2*nj+1][q], v1);
                    }
                    *reinterpret_cast<float2*>(Cf + (size_t)row * OUT_DIM + col) = make_float2(v0, v1);
                }
            }
    }
}

// ---------------------------------------------------------------------------
extern "C" void kernel_launch(void* const* d_in, const int* in_sizes, int n_in,
                              void* d_out, int out_size)
{
    const float* x   = (const float*)d_in[0];
    const float* g2w = (const float*)d_in[1];
    const float* g2b = (const float*)d_in[2];
    const float* g3w = (const float*)d_in[3];
    const float* g3b = (const float*)d_in[4];
    const float* w1  = (const float*)d_in[5];
    const float* b1  = (const float*)d_in[6];
    const float* w2  = (const float*)d_in[7];
    const float* b2  = (const float*)d_in[8];
    float* out = (float*)d_out;

    const int B = in_sizes[0] / IN_DIM;   // 32768

    float* gate;
    __half *xh, *w1hi, *w1lo, *w2hi, *w2lo, *hs;
    cudaGetSymbolAddress((void**)&gate, g_gate);
    cudaGetSymbolAddress((void**)&xh, g_xh);
    cudaGetSymbolAddress((void**)&w1hi, g_w1hi);
    cudaGetSymbolAddress((void**)&w1lo, g_w1lo);
    cudaGetSymbolAddress((void**)&w2hi, g_w2hi);
    cudaGetSymbolAddress((void**)&w2lo, g_w2lo);
    cudaGetSymbolAddress((void**)&hs, g_hs);

    cudaFuncSetAttribute(gemm_mma<IN_DIM, true>,
                         cudaFuncAttributeMaxDynamicSharedMemorySize, SMEM_TOTAL);
    cudaFuncSetAttribute(gemm_mma<H3, false>,
                         cudaFuncAttributeMaxDynamicSharedMemorySize, SMEM_TOTAL);

    // 1) gate + fp16 quantize x
    gate_split_kernel<<<(B + 7) / 8, 256>>>(x, g2w, g2b, g3w, g3b, gate, xh, B);

    // 2) transpose+split weights (fp16 hi/lo)
    transplit_kernel<<<dim3(HID_DIM/32, IN_DIM/32, N_EXP), dim3(32, 8)>>>(w1, w1hi, w1lo, IN_DIM, HID_DIM);
    transplit_kernel<<<dim3(OUT_DIM/32, H3/32, 1),        dim3(32, 8)>>>(w2, w2hi, w2lo, H3, OUT_DIM);

    // 3) hs = fp16(relu(x @ W1 + b1) * gate)   [B,3072]  (2-pass: W1 hi+lo)
    gemm_mma<IN_DIM, true><<<dim3(H3/BN, B/BM), 256, SMEM_TOTAL>>>(
        xh, w1hi, w1lo, b1, gate, hs, nullptr);

    // 4) out = hs @ W2 + gate @ b2             [B,1024]  (2-pass: W2 hi+lo)
    gemm_mma<H3, false><<<dim3(OUT_DIM/BN, B/BM), 256, SMEM_TOTAL>>>(
        hs, w2hi, w2lo, b2, gate, nullptr, out);
}

// round 11
// speedup vs baseline: 3.2289x; 1.6041x over previous
#include <cuda_runtime.h>
#include <cuda_fp16.h>
#include <cstdint>
#include <cstddef>

#define IN_DIM   1024
#define HID_DIM  512
#define OUT_DIM  1024
#define N_EXP    6
#define H3       3072
#define MAXB     32768

// ---------------- scratch (device globals; no allocation allowed) ----------
__device__ float  g_gate[(size_t)MAXB * N_EXP];
__device__ __half g_xh [(size_t)MAXB * IN_DIM];    // fp16(x)
__device__ __half g_w1 [(size_t)H3 * IN_DIM];      // fp16(W1^T) [3072,1024] K contig
__device__ __half g_w2 [(size_t)OUT_DIM * H3];     // fp16(W2^T) [1024,3072] K contig
__device__ __half g_hs [(size_t)MAXB * H3];        // fp16 hidden

// ---------------- helpers ---------------------------------------------------
__device__ __forceinline__ uint32_t smem_u32(const void* p) {
    uint32_t a;
    asm("{ .reg .u64 t; cvta.to.shared.u64 t, %1; cvt.u32.u64 %0, t; }" : "=r"(a) : "l"(p));
    return a;
}
__device__ __forceinline__ void cp16(uint32_t dst, const void* src) {
    asm volatile("cp.async.cg.shared.global [%0], [%1], 16;" :: "r"(dst), "l"(src));
}
__device__ __forceinline__ void cp_commit() {
    asm volatile("cp.async.commit_group;" ::: "memory");
}
template <int N>
__device__ __forceinline__ void cp_wait() {
    asm volatile("cp.async.wait_group %0;" :: "n"(N) : "memory");
}
__device__ __forceinline__ void ldsm4(uint32_t* r, uint32_t addr) {
    asm volatile("ldmatrix.sync.aligned.m8n8.x4.shared.b16 {%0,%1,%2,%3}, [%4];"
                 : "=r"(r[0]), "=r"(r[1]), "=r"(r[2]), "=r"(r[3]) : "r"(addr));
}
__device__ __forceinline__ void mma_f16(float* c, const uint32_t* a, const uint32_t* b) {
    asm volatile(
        "mma.sync.aligned.m16n8k16.row.col.f32.f16.f16.f32 "
        "{%0,%1,%2,%3}, {%4,%5,%6,%7}, {%8,%9}, {%0,%1,%2,%3};"
        : "+f"(c[0]), "+f"(c[1]), "+f"(c[2]), "+f"(c[3])
        : "r"(a[0]), "r"(a[1]), "r"(a[2]), "r"(a[3]), "r"(b[0]), "r"(b[1]));
}
// 64B rows, 16B chunks, xor-swizzle (conflict-free ldmatrix)
__device__ __forceinline__ int sw_off(int row, int chunk) {
    return row * 64 + ((chunk ^ ((row >> 1) & 3)) << 4);
}
__device__ __forceinline__ uint32_t pk_h2(float v0, float v1) {
    __half2 h = __halves2half2(__float2half_rn(v0), __float2half_rn(v1));
    return *reinterpret_cast<uint32_t*>(&h);
}

// ---------------- fused gate + fp16 quantize of x ---------------------------
__global__ __launch_bounds__(256) void gate_split_kernel(
    const float* __restrict__ x,
    const float* __restrict__ g2w, const float* __restrict__ g2b,
    const float* __restrict__ g3w, const float* __restrict__ g3b,
    float* __restrict__ gate, __half* __restrict__ xh, int B)
{
    int row  = (blockIdx.x * 256 + threadIdx.x) >> 5;
    int lane = threadIdx.x & 31;
    if (row >= B) return;

    const float4* xr = reinterpret_cast<const float4*>(x + (size_t)row * IN_DIM);
    float a0 = 0.f, a1 = 0.f, a2 = 0.f, a3 = 0.f;
    #pragma unroll
    for (int j = 0; j < 8; ++j) {
        int i = lane + j * 32;
        float4 v = xr[i];
        int k = i * 4;
        a0 = fmaf(v.x, g2w[k], fmaf(v.y, g2w[k+1], fmaf(v.z, g2w[k+2], fmaf(v.w, g2w[k+3], a0))));
        a1 = fmaf(v.x, g3w[k*3+0], fmaf(v.y, g3w[(k+1)*3+0], fmaf(v.z, g3w[(k+2)*3+0], fmaf(v.w, g3w[(k+3)*3+0], a1))));
        a2 = fmaf(v.x, g3w[k*3+1], fmaf(v.y, g3w[(k+1)*3+1], fmaf(v.z, g3w[(k+2)*3+1], fmaf(v.w, g3w[(k+3)*3+1], a2))));
        a3 = fmaf(v.x, g3w[k*3+2], fmaf(v.y, g3w[(k+1)*3+2], fmaf(v.z, g3w[(k+2)*3+2], fmaf(v.w, g3w[(k+3)*3+2], a3))));
        *reinterpret_cast<uint2*>(xh + (size_t)row * IN_DIM + k) =
            make_uint2(pk_h2(v.x, v.y), pk_h2(v.z, v.w));
    }
    #pragma unroll
    for (int off = 16; off > 0; off >>= 1) {
        a0 += __shfl_down_sync(0xffffffffu, a0, off);
        a1 += __shfl_down_sync(0xffffffffu, a1, off);
        a2 += __shfl_down_sync(0xffffffffu, a2, off);
        a3 += __shfl_down_sync(0xffffffffu, a3, off);
    }
    if (lane == 0) {
        float alpha = 1.f / (1.f + expf(-(a0 + g2b[0])));
        float l0 = a1 + g3b[0], l1 = a2 + g3b[1], l2 = a3 + g3b[2];
        float m = fmaxf(l0, fmaxf(l1, l2));
        float e0 = expf(l0 - m), e1 = expf(l1 - m), e2 = expf(l2 - m);
        float inv = 1.f / (e0 + e1 + e2);
        float p0 = e0 * inv, p1 = e1 * inv, p2 = e2 * inv, ga = 1.f - alpha;
        float* o = gate + (size_t)row * N_EXP;
        o[0] = ga * p0;    o[1] = ga * p1;    o[2] = ga * p2;
        o[3] = alpha * p0; o[4] = alpha * p1; o[5] = alpha * p2;
    }
}

// -------- transpose + quantize: src[R,C] fp32 -> dst[C,R] fp16 --------------
__global__ void transquant_kernel(const float* __restrict__ src,
                                  __half* __restrict__ dst, int R, int C)
{
    __shared__ float t[32][33];
    size_t zoff = (size_t)blockIdx.z * R * C;
    int c0 = blockIdx.x * 32, r0 = blockIdx.y * 32;
    int tx = threadIdx.x, ty = threadIdx.y;          // 32 x 8
    #pragma unroll
    for (int i = 0; i < 4; ++i)
        t[ty + i*8][tx] = src[zoff + (size_t)(r0 + ty + i*8) * C + c0 + tx];
    __syncthreads();
    #pragma unroll
    for (int i = 0; i < 4; ++i) {
        int c = c0 + ty + i*8, r = r0 + tx;
        dst[zoff + (size_t)c * R + r] = __float2half_rn(t[tx][ty + i*8]);
    }
}

// ================== plain 1-pass fp16 GEMM ==================================
// CTA 128x128, BK=32, 8 warps (2Mx4N), warp 64x32, fp32 acc, 5-stage pipeline.
// FIRST epilogue: hs = fp16(relu(acc + b1) * gate)
// else:           out = acc + gate @ b2   (fp32)
#define BM 128
#define BN 128
#define BK 32
#define STAGES 5
#define STAGE_BYTES 16384   // A 8K | B 8K
#define SMEM_TOTAL (STAGES * STAGE_BYTES)

template <int K, bool FIRST>
__global__ __launch_bounds__(256, 2) void gemm_mma(
    const __half* __restrict__ A, const __half* __restrict__ Bw,
    const float* __restrict__ bias, const float* __restrict__ gate,
    __half* __restrict__ Chs, float* __restrict__ Cf)
{
    extern __shared__ char smem[];
    const uint32_t sbase = smem_u32(smem);
    const int tid  = threadIdx.x;
    const int wid  = tid >> 5;
    const int lane = tid & 31;
    const int mBlk = blockIdx.y * BM;
    const int nBlk = blockIdx.x * BN;
    const int wm = (wid >> 2) * 64;
    const int wn = (wid & 3) * 32;
    constexpr int NK = K / BK;

    const __half* srcTab[2];
    srcTab[0] = A  + (size_t)mBlk * K;
    srcTab[1] = Bw + (size_t)nBlk * K;

    float acc[4][4][4];
    #pragma unroll
    for (int i = 0; i < 4; ++i)
        #pragma unroll
        for (int j = 0; j < 4; ++j)
            #pragma unroll
            for (int q = 0; q < 4; ++q) acc[i][j][q] = 0.f;

    auto load_stage = [&](int s) {
        const int k0 = s * BK;
        const uint32_t sb = sbase + (s % STAGES) * STAGE_BYTES;
        #pragma unroll
        for (int j = 0; j < 4; ++j) {
            int idx = tid + j * 256;          // 0..1023
            int reg = idx >> 9;               // 0=A, 1=B
            int i = idx & 511;
            int row = i >> 2, c = i & 3;
            cp16(sb + reg * 8192 + sw_off(row, c),
                 srcTab[reg] + (size_t)row * K + k0 + c * 8);
        }
        cp_commit();
    };

    #pragma unroll
    for (int s = 0; s < STAGES - 1; ++s) load_stage(s);

    const int rA = wm + (lane & 15);
    const int rB = wn + ((lane >> 4) << 3) + (lane & 7);
    const int cAoff = lane >> 4;
    const int cBoff = (lane >> 3) & 1;

    #pragma unroll 5
    for (int s = 0; s < NK; ++s) {
        cp_wait<STAGES - 2>();
        __syncthreads();
        const uint32_t sb = sbase + (s % STAGES) * STAGE_BYTES;

        uint32_t Ah[4][4], Bh[4][2];
        #pragma unroll
        for (int mi = 0; mi < 4; ++mi)
            ldsm4(Ah[mi], sb + sw_off(rA + 16 * mi, cAoff));
        #pragma unroll
        for (int jp = 0; jp < 2; ++jp) {
            uint32_t t[4];
            ldsm4(t, sb + 8192 + sw_off(rB + 16 * jp, cBoff));
            Bh[2*jp][0] = t[0]; Bh[2*jp][1] = t[1];
            Bh[2*jp+1][0] = t[2]; Bh[2*jp+1][1] = t[3];
        }

        if (s + STAGES - 1 < NK) load_stage(s + STAGES - 1);
        else cp_commit();

        #pragma unroll
        for (int kk = 0; kk < 2; ++kk) {
            uint32_t An[4][4], Bn[4][2];
            if (kk == 0) {   // prefetch kk1 fragments under kk0 MMAs
                #pragma unroll
                for (int mi = 0; mi < 4; ++mi)
                    ldsm4(An[mi], sb + sw_off(rA + 16 * mi, 2 + cAoff));
                #pragma unroll
                for (int jp = 0; jp < 2; ++jp) {
                    uint32_t t[4];
                    ldsm4(t, sb + 8192 + sw_off(rB + 16 * jp, 2 + cBoff));
                    Bn[2*jp][0] = t[0]; Bn[2*jp][1] = t[1];
                    Bn[2*jp+1][0] = t[2]; Bn[2*jp+1][1] = t[3];
                }
            }
            #pragma unroll
            for (int mi = 0; mi < 4; ++mi)
                #pragma unroll
                for (int nj = 0; nj < 4; ++nj)
                    mma_f16(acc[mi][nj], Ah[mi], Bh[nj]);
            if (kk == 0) {
                #pragma unroll
                for (int mi = 0; mi < 4; ++mi)
                    #pragma unroll
                    for (int q = 0; q < 4; ++q) Ah[mi][q] = An[mi][q];
                #pragma unroll
                for (int nj = 0; nj < 4; ++nj) {
                    Bh[nj][0] = Bn[nj][0]; Bh[nj][1] = Bn[nj][1];
                }
            }
        }
    }

    // ---- epilogue ----
    if constexpr (FIRST) {
        const int e = nBlk >> 9;
        float bcol[8];
        #pragma unroll
        for (int nj = 0; nj < 4; ++nj) {
            const int col = nBlk + wn + 8 * nj + 2 * (lane & 3);
            const int bc = e * HID_DIM + (col & (HID_DIM - 1));
            bcol[2*nj]   = bias[bc];
            bcol[2*nj+1] = bias[bc + 1];
        }
        #pragma unroll
        for (int mi = 0; mi < 4; ++mi)
            #pragma unroll
            for (int h = 0; h < 2; ++h) {
                const int row = mBlk + wm + 16 * mi + (lane >> 2) + 8 * h;
                const float g = gate[(size_t)row * N_EXP + e];
                #pragma unroll
                for (int nj = 0; nj < 4; ++nj) {
                    const int col = nBlk + wn + 8 * nj + 2 * (lane & 3);
                    float v0 = fmaxf(acc[mi][nj][2*h]   + bcol[2*nj],   0.f) * g;
                    float v1 = fmaxf(acc[mi][nj][2*h+1] + bcol[2*nj+1], 0.f) * g;
                    *reinterpret_cast<uint32_t*>(Chs + (size_t)row * H3 + col) = pk_h2(v0, v1);
                }
            }
    } else {
        float bb[8][N_EXP];
        #pragma unroll
        for (int nj = 0; nj < 4; ++nj) {
            const int col = nBlk + wn + 8 * nj + 2 * (lane & 3);
            #pragma unroll
            for (int q = 0; q < N_EXP; ++q) {
                bb[2*nj][q]   = bias[q * OUT_DIM + col];
                bb[2*nj+1][q] = bias[q * OUT_DIM + col + 1];
            }
        }
        #pragma unroll
        for (int mi = 0; mi < 4; ++mi)
            #pragma unroll
            for (int h = 0; h < 2; ++h) {
                const int row = mBlk + wm + 16 * mi + (lane >> 2) + 8 * h;
                const float2* gp = reinterpret_cast<const float2*>(gate + (size_t)row * N_EXP);
                float2 gA = gp[0], gB = gp[1], gC = gp[2];
                float gw[N_EXP] = {gA.x, gA.y, gB.x, gB.y, gC.x, gC.y};
                #pragma unroll
                for (int nj = 0; nj < 4; ++nj) {
                    const int col = nBlk + wn + 8 * nj + 2 * (lane & 3);
                    float v0 = acc[mi][nj][2*h];
                    float v1 = acc[mi][nj][2*h+1];
                    #pragma unroll
                    for (int q = 0; q < N_EXP; ++q) {
                        v0 = fmaf(gw[q], bb[2*nj][q],   v0);
                        v1 = fmaf(gw[q], bb[2*nj+1][q], v1);
                    }
                    *reinterpret_cast<float2*>(Cf + (size_t)row * OUT_DIM + col) = make_float2(v0, v1);
                }
            }
    }
}

// ---------------------------------------------------------------------------
extern "C" void kernel_launch(void* const* d_in, const int* in_sizes, int n_in,
                              void* d_out, int out_size)
{
    const float* x   = (const float*)d_in[0];
    const float* g2w = (const float*)d_in[1];
    const float* g2b = (const float*)d_in[2];
    const float* g3w = (const float*)d_in[3];
    const float* g3b = (const float*)d_in[4];
    const float* w1  = (const float*)d_in[5];
    const float* b1  = (const float*)d_in[6];
    const float* w2  = (const float*)d_in[7];
    const float* b2  = (const float*)d_in[8];
    float* out = (float*)d_out;

    const int B = in_sizes[0] / IN_DIM;   // 32768

    float* gate;
    __half *xh, *w1q, *w2q, *hs;
    cudaGetSymbolAddress((void**)&gate, g_gate);
    cudaGetSymbolAddress((void**)&xh, g_xh);
    cudaGetSymbolAddress((void**)&w1q, g_w1);
    cudaGetSymbolAddress((void**)&w2q, g_w2);
    cudaGetSymbolAddress((void**)&hs, g_hs);

    cudaFuncSetAttribute(gemm_mma<IN_DIM, true>,
                         cudaFuncAttributeMaxDynamicSharedMemorySize, SMEM_TOTAL);
    cudaFuncSetAttribute(gemm_mma<H3, false>,
                         cudaFuncAttributeMaxDynamicSharedMemorySize, SMEM_TOTAL);

    // 1) gate + fp16 quantize x
    gate_split_kernel<<<(B + 7) / 8, 256>>>(x, g2w, g2b, g3w, g3b, gate, xh, B);

    // 2) transpose + fp16 quantize weights
    transquant_kernel<<<dim3(HID_DIM/32, IN_DIM/32, N_EXP), dim3(32, 8)>>>(w1, w1q, IN_DIM, HID_DIM);
    transquant_kernel<<<dim3(OUT_DIM/32, H3/32, 1),        dim3(32, 8)>>>(w2, w2q, H3, OUT_DIM);

    // 3) hs = fp16(relu(x @ W1 + b1) * gate)   [B,3072]
    gemm_mma<IN_DIM, true><<<dim3(H3/BN, B/BM), 256, SMEM_TOTAL>>>(
        xh, w1q, b1, gate, hs, nullptr);

    // 4) out = hs @ W2 + gate @ b2             [B,1024]
    gemm_mma<H3, false><<<dim3(OUT_DIM/BN, B/BM), 256, SMEM_TOTAL>>>(
        hs, w2q, b2, gate, nullptr, out);
}

// round 12
// speedup vs baseline: 3.2837x; 1.0170x over previous
#include <cuda_runtime.h>
#include <cuda_fp16.h>
#include <cstdint>
#include <cstddef>

#define IN_DIM   1024
#define HID_DIM  512
#define OUT_DIM  1024
#define N_EXP    6
#define H3       3072
#define MAXB     32768

// ---------------- scratch (device globals; no allocation allowed) ----------
__device__ float  g_gate[(size_t)MAXB * N_EXP];
__device__ __half g_xh [(size_t)MAXB * IN_DIM];    // fp16(x)
__device__ __half g_w1 [(size_t)H3 * IN_DIM];      // fp16(W1^T) [3072,1024] K contig
__device__ __half g_w2 [(size_t)OUT_DIM * H3];     // fp16(W2^T) [1024,3072] K contig
__device__ __half g_hs [(size_t)MAXB * H3];        // fp16 hidden

// ---------------- helpers ---------------------------------------------------
__device__ __forceinline__ uint32_t smem_u32(const void* p) {
    uint32_t a;
    asm("{ .reg .u64 t; cvta.to.shared.u64 t, %1; cvt.u32.u64 %0, t; }" : "=r"(a) : "l"(p));
    return a;
}
__device__ __forceinline__ void cp16(uint32_t dst, const void* src) {
    asm volatile("cp.async.cg.shared.global [%0], [%1], 16;" :: "r"(dst), "l"(src));
}
__device__ __forceinline__ void cp_commit() {
    asm volatile("cp.async.commit_group;" ::: "memory");
}
template <int N>
__device__ __forceinline__ void cp_wait() {
    asm volatile("cp.async.wait_group %0;" :: "n"(N) : "memory");
}
__device__ __forceinline__ void ldsm4(uint32_t* r, uint32_t addr) {
    asm volatile("ldmatrix.sync.aligned.m8n8.x4.shared.b16 {%0,%1,%2,%3}, [%4];"
                 : "=r"(r[0]), "=r"(r[1]), "=r"(r[2]), "=r"(r[3]) : "r"(addr));
}
__device__ __forceinline__ void mma_f16(float* c, const uint32_t* a, const uint32_t* b) {
    asm volatile(
        "mma.sync.aligned.m16n8k16.row.col.f32.f16.f16.f32 "
        "{%0,%1,%2,%3}, {%4,%5,%6,%7}, {%8,%9}, {%0,%1,%2,%3};"
        : "+f"(c[0]), "+f"(c[1]), "+f"(c[2]), "+f"(c[3])
        : "r"(a[0]), "r"(a[1]), "r"(a[2]), "r"(a[3]), "r"(b[0]), "r"(b[1]));
}
// 64B rows, 16B chunks, xor-swizzle (conflict-free ldmatrix)
__device__ __forceinline__ int sw_off(int row, int chunk) {
    return row * 64 + ((chunk ^ ((row >> 1) & 3)) << 4);
}
__device__ __forceinline__ uint32_t pk_h2(float v0, float v1) {
    __half2 h = __halves2half2(__float2half_rn(v0), __float2half_rn(v1));
    return *reinterpret_cast<uint32_t*>(&h);
}

// ---------------- fused gate + fp16 quantize of x ---------------------------
__global__ __launch_bounds__(256) void gate_split_kernel(
    const float* __restrict__ x,
    const float* __restrict__ g2w, const float* __restrict__ g2b,
    const float* __restrict__ g3w, const float* __restrict__ g3b,
    float* __restrict__ gate, __half* __restrict__ xh, int B)
{
    int row  = (blockIdx.x * 256 + threadIdx.x) >> 5;
    int lane = threadIdx.x & 31;
    if (row >= B) return;

    const float4* xr = reinterpret_cast<const float4*>(x + (size_t)row * IN_DIM);
    float a0 = 0.f, a1 = 0.f, a2 = 0.f, a3 = 0.f;
    #pragma unroll
    for (int j = 0; j < 8; ++j) {
        int i = lane + j * 32;
        float4 v = xr[i];
        int k = i * 4;
        a0 = fmaf(v.x, g2w[k], fmaf(v.y, g2w[k+1], fmaf(v.z, g2w[k+2], fmaf(v.w, g2w[k+3], a0))));
        a1 = fmaf(v.x, g3w[k*3+0], fmaf(v.y, g3w[(k+1)*3+0], fmaf(v.z, g3w[(k+2)*3+0], fmaf(v.w, g3w[(k+3)*3+0], a1))));
        a2 = fmaf(v.x, g3w[k*3+1], fmaf(v.y, g3w[(k+1)*3+1], fmaf(v.z, g3w[(k+2)*3+1], fmaf(v.w, g3w[(k+3)*3+1], a2))));
        a3 = fmaf(v.x, g3w[k*3+2], fmaf(v.y, g3w[(k+1)*3+2], fmaf(v.z, g3w[(k+2)*3+2], fmaf(v.w, g3w[(k+3)*3+2], a3))));
        *reinterpret_cast<uint2*>(xh + (size_t)row * IN_DIM + k) =
            make_uint2(pk_h2(v.x, v.y), pk_h2(v.z, v.w));
    }
    #pragma unroll
    for (int off = 16; off > 0; off >>= 1) {
        a0 += __shfl_down_sync(0xffffffffu, a0, off);
        a1 += __shfl_down_sync(0xffffffffu, a1, off);
        a2 += __shfl_down_sync(0xffffffffu, a2, off);
        a3 += __shfl_down_sync(0xffffffffu, a3, off);
    }
    if (lane == 0) {
        float alpha = 1.f / (1.f + expf(-(a0 + g2b[0])));
        float l0 = a1 + g3b[0], l1 = a2 + g3b[1], l2 = a3 + g3b[2];
        float m = fmaxf(l0, fmaxf(l1, l2));
        float e0 = expf(l0 - m), e1 = expf(l1 - m), e2 = expf(l2 - m);
        float inv = 1.f / (e0 + e1 + e2);
        float p0 = e0 * inv, p1 = e1 * inv, p2 = e2 * inv, ga = 1.f - alpha;
        float* o = gate + (size_t)row * N_EXP;
        o[0] = ga * p0;    o[1] = ga * p1;    o[2] = ga * p2;
        o[3] = alpha * p0; o[4] = alpha * p1; o[5] = alpha * p2;
    }
}

// -------- transpose + quantize: src[R,C] fp32 -> dst[C,R] fp16 --------------
__global__ void transquant_kernel(const float* __restrict__ src,
                                  __half* __restrict__ dst, int R, int C)
{
    __shared__ float t[32][33];
    size_t zoff = (size_t)blockIdx.z * R * C;
    int c0 = blockIdx.x * 32, r0 = blockIdx.y * 32;
    int tx = threadIdx.x, ty = threadIdx.y;          // 32 x 8
    #pragma unroll
    for (int i = 0; i < 4; ++i)
        t[ty + i*8][tx] = src[zoff + (size_t)(r0 + ty + i*8) * C + c0 + tx];
    __syncthreads();
    #pragma unroll
    for (int i = 0; i < 4; ++i) {
        int c = c0 + ty + i*8, r = r0 + tx;
        dst[zoff + (size_t)c * R + r] = __float2half_rn(t[tx][ty + i*8]);
    }
}

// ================== 1-pass fp16 GEMM, BK=64 =================================
// CTA 128x128, BK=64 (4 k16 chunks/iter), 8 warps (2Mx4N), warp 64x32,
// fp32 acc, 3-stage pipeline (32KB/stage, 96KB/CTA, 2 CTAs/SM = 192KB).
// Stage layout: A: [sub][128 rows][64B] 16KB | B same at +16K.
// FIRST epilogue: hs = fp16(relu(acc + b1) * gate); else out = acc + gate@b2.
#define BM 128
#define BN 128
#define BK 64
#define STAGES 3
#define STAGE_BYTES 32768
#define SMEM_TOTAL (STAGES * STAGE_BYTES)

template <int K, bool FIRST>
__global__ __launch_bounds__(256, 2) void gemm_mma(
    const __half* __restrict__ A, const __half* __restrict__ Bw,
    const float* __restrict__ bias, const float* __restrict__ gate,
    __half* __restrict__ Chs, float* __restrict__ Cf)
{
    extern __shared__ char smem[];
    const uint32_t sbase = smem_u32(smem);
    const int tid  = threadIdx.x;
    const int wid  = tid >> 5;
    const int lane = tid & 31;
    const int mBlk = blockIdx.y * BM;
    const int nBlk = blockIdx.x * BN;
    const int wm = (wid >> 2) * 64;
    const int wn = (wid & 3) * 32;
    constexpr int NK = K / BK;

    const __half* srcTab[2];
    srcTab[0] = A  + (size_t)mBlk * K;
    srcTab[1] = Bw + (size_t)nBlk * K;

    float acc[4][4][4];
    #pragma unroll
    for (int i = 0; i < 4; ++i)
        #pragma unroll
        for (int j = 0; j < 4; ++j)
            #pragma unroll
            for (int q = 0; q < 4; ++q) acc[i][j][q] = 0.f;

    // 2048 16B chunks/stage, 8 per thread.
    // idx: reg = idx>>10 (A/B), i=idx&1023: sub = i>>9, ii=i&511,
    // row = ii>>2, c = ii&3 -> gmem col = sub*32 + c*8
    auto load_stage = [&](int s) {
        const int k0 = s * BK;
        const uint32_t sb = sbase + (s % STAGES) * STAGE_BYTES;
        #pragma unroll
        for (int j = 0; j < 8; ++j) {
            int idx = tid + j * 256;
            int reg = idx >> 10;
            int i = idx & 1023;
            int sub = i >> 9;
            int ii = i & 511;
            int row = ii >> 2, c = ii & 3;
            cp16(sb + reg * 16384 + sub * 8192 + sw_off(row, c),
                 srcTab[reg] + (size_t)row * K + k0 + sub * 32 + c * 8);
        }
        cp_commit();
    };

    #pragma unroll
    for (int s = 0; s < STAGES - 1; ++s) load_stage(s);

    const int rA = wm + (lane & 15);
    const int rB = wn + ((lane >> 4) << 3) + (lane & 7);
    const int cAoff = lane >> 4;
    const int cBoff = (lane >> 3) & 1;

    // fragment loader for k16-chunk kk (0..3) of stage at sb
    auto load_fragsA = [&](uint32_t* dst /*[4][4] flat*/, uint32_t sb, int kk) {
        const uint32_t base = sb + (kk >> 1) * 8192;
        const int c = (kk & 1) * 2 + cAoff;
        #pragma unroll
        for (int mi = 0; mi < 4; ++mi)
            ldsm4(dst + mi * 4, base + sw_off(rA + 16 * mi, c));
    };
    auto load_fragsB = [&](uint32_t* dst /*[4][2] flat*/, uint32_t sb, int kk) {
        const uint32_t base = sb + 16384 + (kk >> 1) * 8192;
        const int c = (kk & 1) * 2 + cBoff;
        #pragma unroll
        for (int jp = 0; jp < 2; ++jp) {
            uint32_t t[4];
            ldsm4(t, base + sw_off(rB + 16 * jp, c));
            dst[(2*jp)*2]     = t[0]; dst[(2*jp)*2+1]   = t[1];
            dst[(2*jp+1)*2]   = t[2]; dst[(2*jp+1)*2+1] = t[3];
        }
    };

    #pragma unroll 3
    for (int s = 0; s < NK; ++s) {
        cp_wait<STAGES - 2>();
        __syncthreads();
        const uint32_t sb = sbase + (s % STAGES) * STAGE_BYTES;

        uint32_t Af[2][16], Bf[2][8];
        load_fragsA(Af[0], sb, 0);
        load_fragsB(Bf[0], sb, 0);

        if (s + STAGES - 1 < NK) load_stage(s + STAGES - 1);
        else cp_commit();

        #pragma unroll
        for (int kk = 0; kk < 4; ++kk) {
            const int cur = kk & 1, nxt = cur ^ 1;
            if (kk < 3) {
                load_fragsA(Af[nxt], sb, kk + 1);
                load_fragsB(Bf[nxt], sb, kk + 1);
            }
            #pragma unroll
            for (int mi = 0; mi < 4; ++mi)
                #pragma unroll
                for (int nj = 0; nj < 4; ++nj)
                    mma_f16(acc[mi][nj], &Af[cur][mi * 4], &Bf[cur][nj * 2]);
        }
    }

    // ---- epilogue ----
    if constexpr (FIRST) {
        const int e = nBlk >> 9;
        float bcol[8];
        #pragma unroll
        for (int nj = 0; nj < 4; ++nj) {
            const int col = nBlk + wn + 8 * nj + 2 * (lane & 3);
            const int bc = e * HID_DIM + (col & (HID_DIM - 1));
            bcol[2*nj]   = bias[bc];
            bcol[2*nj+1] = bias[bc + 1];
        }
        #pragma unroll
        for (int mi = 0; mi < 4; ++mi)
            #pragma unroll
            for (int h = 0; h < 2; ++h) {
                const int row = mBlk + wm + 16 * mi + (lane >> 2) + 8 * h;
                const float g = gate[(size_t)row * N_EXP + e];
                #pragma unroll
                for (int nj = 0; nj < 4; ++nj) {
                    const int col = nBlk + wn + 8 * nj + 2 * (lane & 3);
                    float v0 = fmaxf(acc[mi][nj][2*h]   + bcol[2*nj],   0.f) * g;
                    float v1 = fmaxf(acc[mi][nj][2*h+1] + bcol[2*nj+1], 0.f) * g;
                    *reinterpret_cast<uint32_t*>(Chs + (size_t)row * H3 + col) = pk_h2(v0, v1);
                }
            }
    } else {
        float bb[8][N_EXP];
        #pragma unroll
        for (int nj = 0; nj < 4; ++nj) {
            const int col = nBlk + wn + 8 * nj + 2 * (lane & 3);
            #pragma unroll
            for (int q = 0; q < N_EXP; ++q) {
                bb[2*nj][q]   = bias[q * OUT_DIM + col];
                bb[2*nj+1][q] = bias[q * OUT_DIM + col + 1];
            }
        }
        #pragma unroll
        for (int mi = 0; mi < 4; ++mi)
            #pragma unroll
            for (int h = 0; h < 2; ++h) {
                const int row = mBlk + wm + 16 * mi + (lane >> 2) + 8 * h;
                const float2* gp = reinterpret_cast<const float2*>(gate + (size_t)row * N_EXP);
                float2 gA = gp[0], gB = gp[1], gC = gp[2];
                float gw[N_EXP] = {gA.x, gA.y, gB.x, gB.y, gC.x, gC.y};
                #pragma unroll
                for (int nj = 0; nj < 4; ++nj) {
                    const int col = nBlk + wn + 8 * nj + 2 * (lane & 3);
                    float v0 = acc[mi][nj][2*h];
                    float v1 = acc[mi][nj][2*h+1];
                    #pragma unroll
                    for (int q = 0; q < N_EXP; ++q) {
                        v0 = fmaf(gw[q], bb[2*nj][q],   v0);
                        v1 = fmaf(gw[q], bb[2*nj+1][q], v1);
                    }
                    *reinterpret_cast<float2*>(Cf + (size_t)row * OUT_DIM + col) = make_float2(v0, v1);
                }
            }
    }
}

// ---------------------------------------------------------------------------
extern "C" void kernel_launch(void* const* d_in, const int* in_sizes, int n_in,
                              void* d_out, int out_size)
{
    const float* x   = (const float*)d_in[0];
    const float* g2w = (const float*)d_in[1];
    const float* g2b = (const float*)d_in[2];
    const float* g3w = (const float*)d_in[3];
    const float* g3b = (const float*)d_in[4];
    const float* w1  = (const float*)d_in[5];
    const float* b1  = (const float*)d_in[6];
    const float* w2  = (const float*)d_in[7];
    const float* b2  = (const float*)d_in[8];
    float* out = (float*)d_out;

    const int B = in_sizes[0] / IN_DIM;   // 32768

    float* gate;
    __half *xh, *w1q, *w2q, *hs;
    cudaGetSymbolAddress((void**)&gate, g_gate);
    cudaGetSymbolAddress((void**)&xh, g_xh);
    cudaGetSymbolAddress((void**)&w1q, g_w1);
    cudaGetSymbolAddress((void**)&w2q, g_w2);
    cudaGetSymbolAddress((void**)&hs, g_hs);

    cudaFuncSetAttribute(gemm_mma<IN_DIM, true>,
                         cudaFuncAttributeMaxDynamicSharedMemorySize, SMEM_TOTAL);
    cudaFuncSetAttribute(gemm_mma<H3, false>,
                         cudaFuncAttributeMaxDynamicSharedMemorySize, SMEM_TOTAL);

    // 1) gate + fp16 quantize x
    gate_split_kernel<<<(B + 7) / 8, 256>>>(x, g2w, g2b, g3w, g3b, gate, xh, B);

    // 2) transpose + fp16 quantize weights
    transquant_kernel<<<dim3(HID_DIM/32, IN_DIM/32, N_EXP), dim3(32, 8)>>>(w1, w1q, IN_DIM, HID_DIM);
    transquant_kernel<<<dim3(OUT_DIM/32, H3/32, 1),        dim3(32, 8)>>>(w2, w2q, H3, OUT_DIM);

    // 3) hs = fp16(relu(x @ W1 + b1) * gate)   [B,3072]
    gemm_mma<IN_DIM, true><<<dim3(H3/BN, B/BM), 256, SMEM_TOTAL>>>(
        xh, w1q, b1, gate, hs, nullptr);

    // 4) out = hs @ W2 + gate @ b2             [B,1024]
    gemm_mma<H3, false><<<dim3(OUT_DIM/BN, B/BM), 256, SMEM_TOTAL>>>(
        hs, w2q, b2, gate, nullptr, out);
}